// round 3
// baseline (speedup 1.0000x reference)
#include <cuda_runtime.h>
#include <math.h>

// LCNECortexLSTM: B=65536, D=H=256.
// Pipeline (all intermediates live inside d_out's 5 output sections):
//   k0:  WxWi = Wx@Wi, WxWC = Wx@WC, fused biases; zero BN stat accumulators.
//   k1a: LC_raw = X@Wx + pLC@Wh + (bx+bh)            -> sec0, + BN1 stats
//   k1b: base   = sigmoid(pC@Wf+bf)*cell + X@WxWC+b  -> sec2
//   k1c: igate  = sigmoid(X@WxWi + b)                -> sec3
//   k2 : LC_t = leaky(bn1(LC_raw)) (in-place sec0), NE_raw = LC_t@WLC+bLC -> sec4, + BN2 stats
//   k3 : NE_t = leaky(bn2(NE_raw)) -> sec1, new_cell = base + ig*0.1*(NE_t@WLC+bLC) -> sec4 (in place), + BN3 stats
//   k4 : C_t = leaky(bn3(new_cell)) -> sec2, p[b]=(LC_t+C_t+NE_t)@WP,
//        Pupil = sigmoid(C_t@Wo+bo)*(p+bP) -> sec3

#define BD 65536
#define HD 256
#define BMT 64
#define KC 16
#define NTH 256
#define AST 66

__device__ float g_WxWi[HD * HD];
__device__ float g_WxWC[HD * HD];
__device__ float g_bxWi[HD];
__device__ float g_bxWC[HD];
__device__ float g_stats[6 * HD];  // [sum1,sq1,sum2,sq2,sum3,sq3] per column

__device__ __forceinline__ float sigm(float x) { return 1.0f / (1.0f + expf(-x)); }
__device__ __forceinline__ float lky(float x) { return x > 0.0f ? x : 0.1f * x; }

// ---------------- common GEMM macros ----------------

#define GEMM_VARS                                                     \
    const int tid = threadIdx.x;                                      \
    const int tx = tid & 31, ty = tid >> 5;                           \
    const int row0 = blockIdx.x * BMT;                                \
    const int lr = tid >> 2;                                          \
    const int lk = (tid & 3) * 4;                                     \
    float acc[8][8];                                                  \
    _Pragma("unroll") for (int i_ = 0; i_ < 8; i_++)                  \
        _Pragma("unroll") for (int j_ = 0; j_ < 8; j_++)              \
            acc[i_][j_] = 0.0f;

#define LOAD_B(WPTR, KC0)                                                          \
    {                                                                              \
        _Pragma("unroll") for (int t_ = 0; t_ < 4; t_++) {                         \
            int idx_ = t_ * NTH + tid;                                             \
            int bk_ = idx_ >> 6;                                                   \
            int bc_ = (idx_ & 63) << 2;                                            \
            *(float4*)&Bs[bk_ * HD + bc_] =                                        \
                *(const float4*)((WPTR) + ((KC0) + bk_) * HD + bc_);               \
        }                                                                          \
    }

#define LOAD_A_PLAIN(APTR, KC0)                                                    \
    {                                                                              \
        float4 av_ = *(const float4*)((APTR) + (row0 + lr) * HD + (KC0) + lk);     \
        As[(lk + 0) * AST + lr] = av_.x;                                           \
        As[(lk + 1) * AST + lr] = av_.y;                                           \
        As[(lk + 2) * AST + lr] = av_.z;                                           \
        As[(lk + 3) * AST + lr] = av_.w;                                           \
    }

#define COMPUTE_CHUNK                                                              \
    {                                                                              \
        _Pragma("unroll") for (int kk = 0; kk < KC; kk++) {                        \
            float a_[8];                                                           \
            _Pragma("unroll") for (int i_ = 0; i_ < 8; i_++)                       \
                a_[i_] = As[kk * AST + ty * 8 + i_];                               \
            float4 b0_ = *(float4*)&Bs[kk * HD + tx * 8];                          \
            float4 b1_ = *(float4*)&Bs[kk * HD + tx * 8 + 4];                      \
            float b_[8] = {b0_.x, b0_.y, b0_.z, b0_.w, b1_.x, b1_.y, b1_.z, b1_.w};\
            _Pragma("unroll") for (int i_ = 0; i_ < 8; i_++) {                     \
                _Pragma("unroll") for (int j_ = 0; j_ < 8; j_++)                   \
                    acc[i_][j_] = fmaf(a_[i_], b_[j_], acc[i_][j_]);               \
            }                                                                      \
        }                                                                          \
    }

#define MAINLOOP_PLAIN(APTR, WPTR)                     \
    for (int kc0 = 0; kc0 < HD; kc0 += KC) {           \
        __syncthreads();                               \
        LOAD_A_PLAIN(APTR, kc0);                       \
        LOAD_B(WPTR, kc0);                             \
        __syncthreads();                               \
        COMPUTE_CHUNK;                                 \
    }

// BN-transform-on-load: applies y = leaky(x*scale[k]+shift[k]) while loading A,
// and writes transformed values back to OUTPTR (each element loaded exactly once
// because the block covers the full N=256 width).
#define LOAD_A_TRANS(APTR, OUTPTR, KC0)                                            \
    {                                                                              \
        int aoff_ = (row0 + lr) * HD + (KC0) + lk;                                 \
        float4 av_ = *(const float4*)((APTR) + aoff_);                             \
        float4 tv_;                                                                \
        tv_.x = lky(fmaf(av_.x, sScale[(KC0) + lk + 0], sShift[(KC0) + lk + 0]));  \
        tv_.y = lky(fmaf(av_.y, sScale[(KC0) + lk + 1], sShift[(KC0) + lk + 1]));  \
        tv_.z = lky(fmaf(av_.z, sScale[(KC0) + lk + 2], sShift[(KC0) + lk + 2]));  \
        tv_.w = lky(fmaf(av_.w, sScale[(KC0) + lk + 3], sShift[(KC0) + lk + 3]));  \
        *(float4*)((OUTPTR) + aoff_) = tv_;                                        \
        As[(lk + 0) * AST + lr] = tv_.x;                                           \
        As[(lk + 1) * AST + lr] = tv_.y;                                           \
        As[(lk + 2) * AST + lr] = tv_.z;                                           \
        As[(lk + 3) * AST + lr] = tv_.w;                                           \
    }

#define MAINLOOP_TRANS(APTR, OUTPTR, WPTR)             \
    for (int kc0 = 0; kc0 < HD; kc0 += KC) {           \
        __syncthreads();                               \
        LOAD_A_TRANS(APTR, OUTPTR, kc0);               \
        LOAD_B(WPTR, kc0);                             \
        __syncthreads();                               \
        COMPUTE_CHUNK;                                 \
    }

// As K4's loader, plus accumulation of the Pupil GEMV partial.
#define LOAD_A_TP(APTR, OUTPTR, LCP, NEP, KC0)                                     \
    {                                                                              \
        int aoff_ = (row0 + lr) * HD + (KC0) + lk;                                 \
        float4 av_ = *(const float4*)((APTR) + aoff_);                             \
        float4 tv_;                                                                \
        tv_.x = lky(fmaf(av_.x, sScale[(KC0) + lk + 0], sShift[(KC0) + lk + 0]));  \
        tv_.y = lky(fmaf(av_.y, sScale[(KC0) + lk + 1], sShift[(KC0) + lk + 1]));  \
        tv_.z = lky(fmaf(av_.z, sScale[(KC0) + lk + 2], sShift[(KC0) + lk + 2]));  \
        tv_.w = lky(fmaf(av_.w, sScale[(KC0) + lk + 3], sShift[(KC0) + lk + 3]));  \
        *(float4*)((OUTPTR) + aoff_) = tv_;                                        \
        float4 lv_ = *(const float4*)((LCP) + aoff_);                              \
        float4 nv_ = *(const float4*)((NEP) + aoff_);                              \
        pval = fmaf(tv_.x + lv_.x + nv_.x, sWP[(KC0) + lk + 0], pval);             \
        pval = fmaf(tv_.y + lv_.y + nv_.y, sWP[(KC0) + lk + 1], pval);             \
        pval = fmaf(tv_.z + lv_.z + nv_.z, sWP[(KC0) + lk + 2], pval);             \
        pval = fmaf(tv_.w + lv_.w + nv_.w, sWP[(KC0) + lk + 3], pval);             \
        As[(lk + 0) * AST + lr] = tv_.x;                                           \
        As[(lk + 1) * AST + lr] = tv_.y;                                           \
        As[(lk + 2) * AST + lr] = tv_.z;                                           \
        As[(lk + 3) * AST + lr] = tv_.w;                                           \
    }

#define MAINLOOP_TP(APTR, OUTPTR, LCP, NEP, WPTR)      \
    for (int kc0 = 0; kc0 < HD; kc0 += KC) {           \
        __syncthreads();                               \
        LOAD_A_TP(APTR, OUTPTR, LCP, NEP, kc0);        \
        LOAD_B(WPTR, kc0);                             \
        __syncthreads();                               \
        COMPUTE_CHUNK;                                 \
    }

// Column sum / sumsq of the (final) values held in acc, block-reduced in smem
// (reusing Bs: 8*256 + 8*256 floats = exactly KC*HD), then one atomicAdd per
// column per block.
#define STATS_EPILOG(SIDX)                                                          \
    {                                                                               \
        __syncthreads();                                                            \
        float* rsum_ = Bs;                                                          \
        float* rsq_ = Bs + 8 * HD;                                                  \
        _Pragma("unroll") for (int j_ = 0; j_ < 8; j_++) {                          \
            float s_ = 0.0f, q_ = 0.0f;                                             \
            _Pragma("unroll") for (int i_ = 0; i_ < 8; i_++) {                      \
                float v_ = acc[i_][j_];                                             \
                s_ += v_;                                                           \
                q_ = fmaf(v_, v_, q_);                                              \
            }                                                                       \
            rsum_[ty * HD + tx * 8 + j_] = s_;                                      \
            rsq_[ty * HD + tx * 8 + j_] = q_;                                       \
        }                                                                           \
        __syncthreads();                                                            \
        if (ty == 0) {                                                              \
            _Pragma("unroll") for (int j_ = 0; j_ < 8; j_++) {                      \
                int c_ = tx * 8 + j_;                                               \
                float S_ = 0.0f, Q_ = 0.0f;                                         \
                _Pragma("unroll") for (int t_ = 0; t_ < 8; t_++) {                  \
                    S_ += rsum_[t_ * HD + c_];                                      \
                    Q_ += rsq_[t_ * HD + c_];                                       \
                }                                                                   \
                atomicAdd(&g_stats[(SIDX)*HD + c_], S_);                            \
                atomicAdd(&g_stats[((SIDX) + 1) * HD + c_], Q_);                    \
            }                                                                       \
        }                                                                           \
    }

// Compute per-column BN scale/shift from accumulated stats (biased variance).
#define BN_INIT(SIDX, GAMMA, BETA)                                    \
    __shared__ float sScale[HD];                                      \
    __shared__ float sShift[HD];                                      \
    {                                                                 \
        int h_ = tid;                                                 \
        float m_ = g_stats[(SIDX)*HD + h_] * (1.0f / (float)BD);      \
        float e2_ = g_stats[((SIDX) + 1) * HD + h_] * (1.0f / (float)BD); \
        float rs_ = rsqrtf(e2_ - m_ * m_ + 1e-5f);                    \
        float sc_ = rs_ * (GAMMA)[h_];                                \
        sScale[h_] = sc_;                                             \
        sShift[h_] = (BETA)[h_] - m_ * sc_;                           \
    }

#define STORE_ROWS(OUTPTR)                                            \
    _Pragma("unroll") for (int i_ = 0; i_ < 8; i_++) {                \
        int gr_ = row0 + ty * 8 + i_;                                 \
        float4 v0_ = {acc[i_][0], acc[i_][1], acc[i_][2], acc[i_][3]};\
        float4 v1_ = {acc[i_][4], acc[i_][5], acc[i_][6], acc[i_][7]};\
        *(float4*)((OUTPTR) + gr_ * HD + tx * 8) = v0_;               \
        *(float4*)((OUTPTR) + gr_ * HD + tx * 8 + 4) = v1_;           \
    }

// ---------------- kernels ----------------

// k0: combined weights WxWi = Wx@Wi, WxWC = Wx@WC; fused biases; zero stats.
__global__ void __launch_bounds__(NTH) k0_prep(
    const float* __restrict__ Wx, const float* __restrict__ bx,
    const float* __restrict__ Wi, const float* __restrict__ bi,
    const float* __restrict__ WC, const float* __restrict__ bC) {
    int h = threadIdx.x;
    if (blockIdx.x < HD) {
        __shared__ float sA[HD];
        sA[h] = Wx[blockIdx.x * HD + h];
        __syncthreads();
        float aI = 0.0f, aC = 0.0f;
#pragma unroll 4
        for (int k = 0; k < HD; k++) {
            float a = sA[k];
            aI = fmaf(a, Wi[k * HD + h], aI);
            aC = fmaf(a, WC[k * HD + h], aC);
        }
        g_WxWi[blockIdx.x * HD + h] = aI;
        g_WxWC[blockIdx.x * HD + h] = aC;
    } else {
        float aI = bi[h], aC = bC[h];
        for (int k = 0; k < HD; k++) {
            float a = bx[k];
            aI = fmaf(a, Wi[k * HD + h], aI);
            aC = fmaf(a, WC[k * HD + h], aC);
        }
        g_bxWi[h] = aI;
        g_bxWC[h] = aC;
#pragma unroll
        for (int s = 0; s < 6; s++) g_stats[s * HD + h] = 0.0f;
    }
}

// k1a: LC_raw = X@Wx + pLC@Wh + (bx+bh) -> sec0, + BN1 stats.
__global__ void __launch_bounds__(NTH, 2) k1a(
    const float* __restrict__ X, const float* __restrict__ pLC,
    const float* __restrict__ Wx, const float* __restrict__ Wh,
    const float* __restrict__ bx, const float* __restrict__ bh,
    float* out_lcraw) {
    __shared__ float As[KC * AST];
    __shared__ float Bs[KC * HD];
    GEMM_VARS;
    MAINLOOP_PLAIN(X, Wx);
    MAINLOOP_PLAIN(pLC, Wh);
#pragma unroll
    for (int j = 0; j < 8; j++) {
        int c = tx * 8 + j;
        float bb = __ldg(&bx[c]) + __ldg(&bh[c]);
#pragma unroll
        for (int i = 0; i < 8; i++) acc[i][j] += bb;
    }
    STORE_ROWS(out_lcraw);
    STATS_EPILOG(0);
}

// k1b: base = sigmoid(pC@Wf + bf)*cell + X@WxWC + bxWC -> sec2.
__global__ void __launch_bounds__(NTH, 2) k1b(
    const float* __restrict__ pC, const float* __restrict__ X,
    const float* __restrict__ Wf, const float* __restrict__ bf,
    const float* __restrict__ cell, float* out_base) {
    __shared__ float As[KC * AST];
    __shared__ float Bs[KC * HD];
    GEMM_VARS;
    MAINLOOP_PLAIN(pC, Wf);
    // mid-transform: acc <- sigmoid(acc+bf)*cell
    {
        float bfl[8];
#pragma unroll
        for (int j = 0; j < 8; j++) bfl[j] = __ldg(&bf[tx * 8 + j]);
#pragma unroll
        for (int i = 0; i < 8; i++) {
            int gr = row0 + ty * 8 + i;
            float4 c0 = *(const float4*)(cell + gr * HD + tx * 8);
            float4 c1 = *(const float4*)(cell + gr * HD + tx * 8 + 4);
            float cv[8] = {c0.x, c0.y, c0.z, c0.w, c1.x, c1.y, c1.z, c1.w};
#pragma unroll
            for (int j = 0; j < 8; j++)
                acc[i][j] = sigm(acc[i][j] + bfl[j]) * cv[j];
        }
    }
    MAINLOOP_PLAIN(X, g_WxWC);
#pragma unroll
    for (int j = 0; j < 8; j++) {
        float bb = g_bxWC[tx * 8 + j];
#pragma unroll
        for (int i = 0; i < 8; i++) acc[i][j] += bb;
    }
    STORE_ROWS(out_base);
}

// k1c: igate = sigmoid(X@WxWi + bxWi) -> sec3.
__global__ void __launch_bounds__(NTH, 2) k1c(const float* __restrict__ X, float* out_ig) {
    __shared__ float As[KC * AST];
    __shared__ float Bs[KC * HD];
    GEMM_VARS;
    MAINLOOP_PLAIN(X, g_WxWi);
#pragma unroll
    for (int j = 0; j < 8; j++) {
        float bb = g_bxWi[tx * 8 + j];
#pragma unroll
        for (int i = 0; i < 8; i++) acc[i][j] = sigm(acc[i][j] + bb);
    }
    STORE_ROWS(out_ig);
}

// k2: LC_t = leaky(bn1(LC_raw)) in-place sec0; NE_raw = LC_t@WLC + bLC -> sec4; BN2 stats.
__global__ void __launch_bounds__(NTH, 2) k2(
    float* lcraw_inout, const float* __restrict__ WLC, const float* __restrict__ bLC,
    const float* __restrict__ g1, const float* __restrict__ be1, float* out_neraw) {
    __shared__ float As[KC * AST];
    __shared__ float Bs[KC * HD];
    GEMM_VARS;
    BN_INIT(0, g1, be1);
    MAINLOOP_TRANS(lcraw_inout, lcraw_inout, WLC);
#pragma unroll
    for (int j = 0; j < 8; j++) {
        float bb = __ldg(&bLC[tx * 8 + j]);
#pragma unroll
        for (int i = 0; i < 8; i++) acc[i][j] += bb;
    }
    STORE_ROWS(out_neraw);
    STATS_EPILOG(2);
}

// k3: NE_t = leaky(bn2(NE_raw)) -> sec1; new_cell = base + ig*0.1*(NE_t@WLC + bLC)
//     -> sec4 (in place over NE_raw); BN3 stats.
__global__ void __launch_bounds__(NTH, 2) k3(
    float* neraw_nc, float* out_net, const float* __restrict__ WLC,
    const float* __restrict__ bLC, const float* __restrict__ base,
    const float* __restrict__ ig, const float* __restrict__ g2,
    const float* __restrict__ be2) {
    __shared__ float As[KC * AST];
    __shared__ float Bs[KC * HD];
    GEMM_VARS;
    BN_INIT(2, g2, be2);
    MAINLOOP_TRANS(neraw_nc, out_net, WLC);
    {
        float bL[8];
#pragma unroll
        for (int j = 0; j < 8; j++) bL[j] = __ldg(&bLC[tx * 8 + j]);
#pragma unroll
        for (int i = 0; i < 8; i++) {
            int gr = row0 + ty * 8 + i;
            float4 b0 = *(const float4*)(base + gr * HD + tx * 8);
            float4 b1 = *(const float4*)(base + gr * HD + tx * 8 + 4);
            float4 i0 = *(const float4*)(ig + gr * HD + tx * 8);
            float4 i1 = *(const float4*)(ig + gr * HD + tx * 8 + 4);
            float bv[8] = {b0.x, b0.y, b0.z, b0.w, b1.x, b1.y, b1.z, b1.w};
            float iv[8] = {i0.x, i0.y, i0.z, i0.w, i1.x, i1.y, i1.z, i1.w};
#pragma unroll
            for (int j = 0; j < 8; j++)
                acc[i][j] = fmaf(iv[j] * 0.1f, acc[i][j] + bL[j], bv[j]);
        }
    }
    STORE_ROWS(neraw_nc);
    STATS_EPILOG(4);
}

// k4: C_t = leaky(bn3(new_cell)) -> sec2; p[b] = (LC_t+C_t+NE_t)@WP;
//     Pupil = sigmoid(C_t@Wo + bo) * (p + bP) -> sec3.
__global__ void __launch_bounds__(NTH, 2) k4(
    const float* __restrict__ ncell, float* out_ct,
    const float* __restrict__ lct, const float* __restrict__ net,
    const float* __restrict__ Wo, const float* __restrict__ bo,
    const float* __restrict__ WP, const float* __restrict__ bP,
    const float* __restrict__ g3, const float* __restrict__ be3,
    float* out_pupil) {
    __shared__ float As[KC * AST];
    __shared__ float Bs[KC * HD];
    __shared__ float sWP[HD];
    __shared__ float p_s[BMT];
    GEMM_VARS;
    BN_INIT(4, g3, be3);
    sWP[tid] = WP[tid];
    if (tid < BMT) p_s[tid] = 0.0f;
    float pval = 0.0f;
    MAINLOOP_TP(ncell, out_ct, lct, net, Wo);
    atomicAdd(&p_s[lr], pval);
    __syncthreads();
    {
        float bP0 = __ldg(&bP[0]);
        float bol[8];
#pragma unroll
        for (int j = 0; j < 8; j++) bol[j] = __ldg(&bo[tx * 8 + j]);
#pragma unroll
        for (int i = 0; i < 8; i++) {
            float pr = p_s[ty * 8 + i] + bP0;
#pragma unroll
            for (int j = 0; j < 8; j++)
                acc[i][j] = sigm(acc[i][j] + bol[j]) * pr;
        }
    }
    STORE_ROWS(out_pupil);
}

// ---------------- launch ----------------

extern "C" void kernel_launch(void* const* d_in, const int* in_sizes, int n_in,
                              void* d_out, int out_size) {
    (void)in_sizes; (void)n_in; (void)out_size;
    const float* X    = (const float*)d_in[0];
    const float* pLC  = (const float*)d_in[1];
    const float* pC   = (const float*)d_in[2];
    const float* cell = (const float*)d_in[3];
    const float* Wx = (const float*)d_in[4];   const float* bx = (const float*)d_in[5];
    const float* Wh = (const float*)d_in[6];   const float* bh = (const float*)d_in[7];
    const float* WLC = (const float*)d_in[8];  const float* bLC = (const float*)d_in[9];
    const float* WC = (const float*)d_in[10];  const float* bC = (const float*)d_in[11];
    const float* WP = (const float*)d_in[12];  const float* bP = (const float*)d_in[13];
    const float* Wf = (const float*)d_in[14];  const float* bf = (const float*)d_in[15];
    const float* Wi = (const float*)d_in[16];  const float* bi = (const float*)d_in[17];
    const float* Wo = (const float*)d_in[18];  const float* bo = (const float*)d_in[19];
    const float* g1 = (const float*)d_in[20];  const float* be1 = (const float*)d_in[21];
    const float* g2 = (const float*)d_in[22];  const float* be2 = (const float*)d_in[23];
    const float* g3 = (const float*)d_in[24];  const float* be3 = (const float*)d_in[25];

    float* o = (float*)d_out;
    const size_t SEC = (size_t)BD * HD;
    float* sLC = o;            // LC_t   (holds LC_raw until k2)
    float* sNE = o + SEC;      // NE_t
    float* sCT = o + 2 * SEC;  // C_t    (holds base until k3 consumes it)
    float* sPU = o + 3 * SEC;  // Pupil  (holds igate until k3 consumes it)
    float* sNC = o + 4 * SEC;  // new_cell (holds NE_raw until k3 overwrites)

    dim3 blk(NTH);
    dim3 grd(BD / BMT);

    k0_prep<<<HD + 1, NTH>>>(Wx, bx, Wi, bi, WC, bC);
    k1a<<<grd, blk>>>(X, pLC, Wx, Wh, bx, bh, sLC);
    k1b<<<grd, blk>>>(pC, X, Wf, bf, cell, sCT);
    k1c<<<grd, blk>>>(X, sPU);
    k2<<<grd, blk>>>(sLC, WLC, bLC, g1, be1, sNC);
    k3<<<grd, blk>>>(sNC, sNE, WLC, bLC, sCT, sPU, g2, be2);
    k4<<<grd, blk>>>(sNC, sCT, sLC, sNE, Wo, bo, WP, bP, g3, be3, sPU);
}

// round 4
// speedup vs baseline: 1.4292x; 1.4292x over previous
#include <cuda_runtime.h>
#include <math.h>

// LCNECortexLSTM: B=65536, D=H=256.
// Round 3: packed fma.rn.f32x2 (FFMA2) compute core. A-values stored duplicated
// in shared ((a,a) pairs, read with one LDS.64 broadcast); B pairs come free
// from LDS.128 register adjacency. 32 FFMA2 per k-step instead of 64 FFMA.
//
// Pipeline (all intermediates live inside d_out's 5 output sections):
//   k0:  WxWi = Wx@Wi, WxWC = Wx@WC, fused biases; zero BN stat accumulators.
//   k1a: LC_raw = X@Wx + pLC@Wh + (bx+bh)            -> sec0, + BN1 stats
//   k1b: base   = sigmoid(pC@Wf+bf)*cell + X@WxWC+b  -> sec2
//   k1c: igate  = sigmoid(X@WxWi + b)                -> sec3
//   k2 : LC_t = leaky(bn1(LC_raw)) (in-place sec0), NE_raw = LC_t@WLC+bLC -> sec4, + BN2 stats
//   k3 : NE_t = leaky(bn2(NE_raw)) -> sec1, new_cell = base + ig*0.1*(NE_t@WLC+bLC) -> sec4, + BN3 stats
//   k4 : C_t = leaky(bn3(new_cell)) -> sec2, p[b]=(LC_t+C_t+NE_t)@WP,
//        Pupil = sigmoid(C_t@Wo+bo)*(p+bP) -> sec3

#define BD 65536
#define HD 256
#define BMT 64
#define KC 16
#define NTH 256
#define ASTP 65  // stride of duplicated-A shared tile, in 8-byte units

typedef unsigned long long u64;

__device__ float g_WxWi[HD * HD];
__device__ float g_WxWC[HD * HD];
__device__ float g_bxWi[HD];
__device__ float g_bxWC[HD];
__device__ float g_stats[6 * HD];  // [sum1,sq1,sum2,sq2,sum3,sq3] per column

__device__ __forceinline__ float sigm(float x) { return 1.0f / (1.0f + expf(-x)); }
__device__ __forceinline__ float lky(float x) { return x > 0.0f ? x : 0.1f * x; }

// pack one float into both lanes of a 64-bit register pair
__device__ __forceinline__ u64 dup2(float x) {
    u64 r;
    asm("mov.b64 %0, {%1, %1};" : "=l"(r) : "f"(x));
    return r;
}

__device__ __forceinline__ void ffma2(u64& d, u64 a, u64 b) {
    asm("fma.rn.f32x2 %0, %1, %2, %0;" : "+l"(d) : "l"(a), "l"(b));
}

// acc viewed either as 8x4 packed pairs (compute) or 8x8 floats (epilogue).
// f[i][2*jp+0] = lo lane of u[i][jp], f[i][2*jp+1] = hi lane.
union AccU {
    u64 u[8][4];
    float f[8][8];
};

// ---------------- common GEMM macros ----------------

#define GEMM_VARS                                                     \
    const int tid = threadIdx.x;                                      \
    const int tx = tid & 31, ty = tid >> 5;                           \
    const int row0 = blockIdx.x * BMT;                                \
    const int lr = tid >> 2;                                          \
    const int lk = (tid & 3) * 4;                                     \
    AccU acc;                                                         \
    _Pragma("unroll") for (int i_ = 0; i_ < 8; i_++)                  \
        _Pragma("unroll") for (int j_ = 0; j_ < 4; j_++)              \
            acc.u[i_][j_] = 0ULL;

#define LOAD_B(WPTR, KC0)                                                          \
    {                                                                              \
        _Pragma("unroll") for (int t_ = 0; t_ < 4; t_++) {                         \
            int idx_ = t_ * NTH + tid;                                             \
            int bk_ = idx_ >> 6;                                                   \
            int bc_ = (idx_ & 63) << 2;                                            \
            *(float4*)&Bs[bk_ * HD + bc_] =                                        \
                *(const float4*)((WPTR) + ((KC0) + bk_) * HD + bc_);               \
        }                                                                          \
    }

#define LOAD_A_PLAIN(APTR, KC0)                                                    \
    {                                                                              \
        float4 av_ = *(const float4*)((APTR) + (row0 + lr) * HD + (KC0) + lk);     \
        As2[(lk + 0) * ASTP + lr] = dup2(av_.x);                                   \
        As2[(lk + 1) * ASTP + lr] = dup2(av_.y);                                   \
        As2[(lk + 2) * ASTP + lr] = dup2(av_.z);                                   \
        As2[(lk + 3) * ASTP + lr] = dup2(av_.w);                                   \
    }

#define COMPUTE_CHUNK                                                              \
    {                                                                              \
        _Pragma("unroll") for (int kk = 0; kk < KC; kk++) {                        \
            u64 a64_[8];                                                           \
            _Pragma("unroll") for (int i_ = 0; i_ < 8; i_++)                       \
                a64_[i_] = As2[kk * ASTP + ty * 8 + i_];                           \
            ulonglong2 bb0_ = *(const ulonglong2*)&Bs[kk * HD + tx * 8];           \
            ulonglong2 bb1_ = *(const ulonglong2*)&Bs[kk * HD + tx * 8 + 4];       \
            u64 b64_[4] = {bb0_.x, bb0_.y, bb1_.x, bb1_.y};                        \
            _Pragma("unroll") for (int i_ = 0; i_ < 8; i_++) {                     \
                _Pragma("unroll") for (int j_ = 0; j_ < 4; j_++)                   \
                    ffma2(acc.u[i_][j_], a64_[i_], b64_[j_]);                      \
            }                                                                      \
        }                                                                          \
    }

#define MAINLOOP_PLAIN(APTR, WPTR)                     \
    for (int kc0 = 0; kc0 < HD; kc0 += KC) {           \
        __syncthreads();                               \
        LOAD_A_PLAIN(APTR, kc0);                       \
        LOAD_B(WPTR, kc0);                             \
        __syncthreads();                               \
        COMPUTE_CHUNK;                                 \
    }

// BN-transform-on-load: y = leaky(x*scale[k]+shift[k]) applied while loading A;
// transformed values written to OUTPTR (each element loaded exactly once since
// the block covers the full N=256 width).
#define LOAD_A_TRANS(APTR, OUTPTR, KC0)                                            \
    {                                                                              \
        int aoff_ = (row0 + lr) * HD + (KC0) + lk;                                 \
        float4 av_ = *(const float4*)((APTR) + aoff_);                             \
        float4 tv_;                                                                \
        tv_.x = lky(fmaf(av_.x, sScale[(KC0) + lk + 0], sShift[(KC0) + lk + 0]));  \
        tv_.y = lky(fmaf(av_.y, sScale[(KC0) + lk + 1], sShift[(KC0) + lk + 1]));  \
        tv_.z = lky(fmaf(av_.z, sScale[(KC0) + lk + 2], sShift[(KC0) + lk + 2]));  \
        tv_.w = lky(fmaf(av_.w, sScale[(KC0) + lk + 3], sShift[(KC0) + lk + 3]));  \
        *(float4*)((OUTPTR) + aoff_) = tv_;                                        \
        As2[(lk + 0) * ASTP + lr] = dup2(tv_.x);                                   \
        As2[(lk + 1) * ASTP + lr] = dup2(tv_.y);                                   \
        As2[(lk + 2) * ASTP + lr] = dup2(tv_.z);                                   \
        As2[(lk + 3) * ASTP + lr] = dup2(tv_.w);                                   \
    }

#define MAINLOOP_TRANS(APTR, OUTPTR, WPTR)             \
    for (int kc0 = 0; kc0 < HD; kc0 += KC) {           \
        __syncthreads();                               \
        LOAD_A_TRANS(APTR, OUTPTR, kc0);               \
        LOAD_B(WPTR, kc0);                             \
        __syncthreads();                               \
        COMPUTE_CHUNK;                                 \
    }

// As K4's loader, plus accumulation of the Pupil GEMV partial.
#define LOAD_A_TP(APTR, OUTPTR, LCP, NEP, KC0)                                     \
    {                                                                              \
        int aoff_ = (row0 + lr) * HD + (KC0) + lk;                                 \
        float4 av_ = *(const float4*)((APTR) + aoff_);                             \
        float4 tv_;                                                                \
        tv_.x = lky(fmaf(av_.x, sScale[(KC0) + lk + 0], sShift[(KC0) + lk + 0]));  \
        tv_.y = lky(fmaf(av_.y, sScale[(KC0) + lk + 1], sShift[(KC0) + lk + 1]));  \
        tv_.z = lky(fmaf(av_.z, sScale[(KC0) + lk + 2], sShift[(KC0) + lk + 2]));  \
        tv_.w = lky(fmaf(av_.w, sScale[(KC0) + lk + 3], sShift[(KC0) + lk + 3]));  \
        *(float4*)((OUTPTR) + aoff_) = tv_;                                        \
        float4 lv_ = *(const float4*)((LCP) + aoff_);                              \
        float4 nv_ = *(const float4*)((NEP) + aoff_);                              \
        pval = fmaf(tv_.x + lv_.x + nv_.x, sWP[(KC0) + lk + 0], pval);             \
        pval = fmaf(tv_.y + lv_.y + nv_.y, sWP[(KC0) + lk + 1], pval);             \
        pval = fmaf(tv_.z + lv_.z + nv_.z, sWP[(KC0) + lk + 2], pval);             \
        pval = fmaf(tv_.w + lv_.w + nv_.w, sWP[(KC0) + lk + 3], pval);             \
        As2[(lk + 0) * ASTP + lr] = dup2(tv_.x);                                   \
        As2[(lk + 1) * ASTP + lr] = dup2(tv_.y);                                   \
        As2[(lk + 2) * ASTP + lr] = dup2(tv_.z);                                   \
        As2[(lk + 3) * ASTP + lr] = dup2(tv_.w);                                   \
    }

#define MAINLOOP_TP(APTR, OUTPTR, LCP, NEP, WPTR)      \
    for (int kc0 = 0; kc0 < HD; kc0 += KC) {           \
        __syncthreads();                               \
        LOAD_A_TP(APTR, OUTPTR, LCP, NEP, kc0);        \
        LOAD_B(WPTR, kc0);                             \
        __syncthreads();                               \
        COMPUTE_CHUNK;                                 \
    }

// Column sum / sumsq of the final values held in acc, block-reduced in smem
// (reusing Bs), then one atomicAdd per column per block.
#define STATS_EPILOG(SIDX)                                                          \
    {                                                                               \
        __syncthreads();                                                            \
        float* rsum_ = Bs;                                                          \
        float* rsq_ = Bs + 8 * HD;                                                  \
        _Pragma("unroll") for (int j_ = 0; j_ < 8; j_++) {                          \
            float s_ = 0.0f, q_ = 0.0f;                                             \
            _Pragma("unroll") for (int i_ = 0; i_ < 8; i_++) {                      \
                float v_ = acc.f[i_][j_];                                           \
                s_ += v_;                                                           \
                q_ = fmaf(v_, v_, q_);                                              \
            }                                                                       \
            rsum_[ty * HD + tx * 8 + j_] = s_;                                      \
            rsq_[ty * HD + tx * 8 + j_] = q_;                                       \
        }                                                                           \
        __syncthreads();                                                            \
        if (ty == 0) {                                                              \
            _Pragma("unroll") for (int j_ = 0; j_ < 8; j_++) {                      \
                int c_ = tx * 8 + j_;                                               \
                float S_ = 0.0f, Q_ = 0.0f;                                         \
                _Pragma("unroll") for (int t_ = 0; t_ < 8; t_++) {                  \
                    S_ += rsum_[t_ * HD + c_];                                      \
                    Q_ += rsq_[t_ * HD + c_];                                       \
                }                                                                   \
                atomicAdd(&g_stats[(SIDX)*HD + c_], S_);                            \
                atomicAdd(&g_stats[((SIDX) + 1) * HD + c_], Q_);                    \
            }                                                                       \
        }                                                                           \
    }

// Compute per-column BN scale/shift from accumulated stats (biased variance).
#define BN_INIT(SIDX, GAMMA, BETA)                                    \
    __shared__ float sScale[HD];                                      \
    __shared__ float sShift[HD];                                      \
    {                                                                 \
        int h_ = tid;                                                 \
        float m_ = g_stats[(SIDX)*HD + h_] * (1.0f / (float)BD);      \
        float e2_ = g_stats[((SIDX) + 1) * HD + h_] * (1.0f / (float)BD); \
        float rs_ = rsqrtf(e2_ - m_ * m_ + 1e-5f);                    \
        float sc_ = rs_ * (GAMMA)[h_];                                \
        sScale[h_] = sc_;                                             \
        sShift[h_] = (BETA)[h_] - m_ * sc_;                           \
    }

#define STORE_ROWS(OUTPTR)                                                    \
    _Pragma("unroll") for (int i_ = 0; i_ < 8; i_++) {                        \
        int gr_ = row0 + ty * 8 + i_;                                         \
        float4 v0_ = {acc.f[i_][0], acc.f[i_][1], acc.f[i_][2], acc.f[i_][3]};\
        float4 v1_ = {acc.f[i_][4], acc.f[i_][5], acc.f[i_][6], acc.f[i_][7]};\
        *(float4*)((OUTPTR) + gr_ * HD + tx * 8) = v0_;                       \
        *(float4*)((OUTPTR) + gr_ * HD + tx * 8 + 4) = v1_;                   \
    }

// ---------------- kernels ----------------

// k0: combined weights WxWi = Wx@Wi, WxWC = Wx@WC; fused biases; zero stats.
__global__ void __launch_bounds__(NTH) k0_prep(
    const float* __restrict__ Wx, const float* __restrict__ bx,
    const float* __restrict__ Wi, const float* __restrict__ bi,
    const float* __restrict__ WC, const float* __restrict__ bC) {
    int h = threadIdx.x;
    if (blockIdx.x < HD) {
        __shared__ float sA[HD];
        sA[h] = Wx[blockIdx.x * HD + h];
        __syncthreads();
        float aI = 0.0f, aC = 0.0f;
#pragma unroll 4
        for (int k = 0; k < HD; k++) {
            float a = sA[k];
            aI = fmaf(a, Wi[k * HD + h], aI);
            aC = fmaf(a, WC[k * HD + h], aC);
        }
        g_WxWi[blockIdx.x * HD + h] = aI;
        g_WxWC[blockIdx.x * HD + h] = aC;
    } else {
        float aI = bi[h], aC = bC[h];
        for (int k = 0; k < HD; k++) {
            float a = bx[k];
            aI = fmaf(a, Wi[k * HD + h], aI);
            aC = fmaf(a, WC[k * HD + h], aC);
        }
        g_bxWi[h] = aI;
        g_bxWC[h] = aC;
#pragma unroll
        for (int s = 0; s < 6; s++) g_stats[s * HD + h] = 0.0f;
    }
}

// k1a: LC_raw = X@Wx + pLC@Wh + (bx+bh) -> sec0, + BN1 stats.
__global__ void __launch_bounds__(NTH, 2) k1a(
    const float* __restrict__ X, const float* __restrict__ pLC,
    const float* __restrict__ Wx, const float* __restrict__ Wh,
    const float* __restrict__ bx, const float* __restrict__ bh,
    float* out_lcraw) {
    __shared__ u64 As2[KC * ASTP];
    __shared__ float Bs[KC * HD];
    GEMM_VARS;
    MAINLOOP_PLAIN(X, Wx);
    MAINLOOP_PLAIN(pLC, Wh);
#pragma unroll
    for (int j = 0; j < 8; j++) {
        int c = tx * 8 + j;
        float bb = __ldg(&bx[c]) + __ldg(&bh[c]);
#pragma unroll
        for (int i = 0; i < 8; i++) acc.f[i][j] += bb;
    }
    STORE_ROWS(out_lcraw);
    STATS_EPILOG(0);
}

// k1b: base = sigmoid(pC@Wf + bf)*cell + X@WxWC + bxWC -> sec2.
__global__ void __launch_bounds__(NTH, 2) k1b(
    const float* __restrict__ pC, const float* __restrict__ X,
    const float* __restrict__ Wf, const float* __restrict__ bf,
    const float* __restrict__ cell, float* out_base) {
    __shared__ u64 As2[KC * ASTP];
    __shared__ float Bs[KC * HD];
    GEMM_VARS;
    MAINLOOP_PLAIN(pC, Wf);
    // mid-transform: acc <- sigmoid(acc+bf)*cell
    {
        float bfl[8];
#pragma unroll
        for (int j = 0; j < 8; j++) bfl[j] = __ldg(&bf[tx * 8 + j]);
#pragma unroll
        for (int i = 0; i < 8; i++) {
            int gr = row0 + ty * 8 + i;
            float4 c0 = *(const float4*)(cell + gr * HD + tx * 8);
            float4 c1 = *(const float4*)(cell + gr * HD + tx * 8 + 4);
            float cv[8] = {c0.x, c0.y, c0.z, c0.w, c1.x, c1.y, c1.z, c1.w};
#pragma unroll
            for (int j = 0; j < 8; j++)
                acc.f[i][j] = sigm(acc.f[i][j] + bfl[j]) * cv[j];
        }
    }
    MAINLOOP_PLAIN(X, g_WxWC);
#pragma unroll
    for (int j = 0; j < 8; j++) {
        float bb = g_bxWC[tx * 8 + j];
#pragma unroll
        for (int i = 0; i < 8; i++) acc.f[i][j] += bb;
    }
    STORE_ROWS(out_base);
}

// k1c: igate = sigmoid(X@WxWi + bxWi) -> sec3.
__global__ void __launch_bounds__(NTH, 2) k1c(const float* __restrict__ X, float* out_ig) {
    __shared__ u64 As2[KC * ASTP];
    __shared__ float Bs[KC * HD];
    GEMM_VARS;
    MAINLOOP_PLAIN(X, g_WxWi);
#pragma unroll
    for (int j = 0; j < 8; j++) {
        float bb = g_bxWi[tx * 8 + j];
#pragma unroll
        for (int i = 0; i < 8; i++) acc.f[i][j] = sigm(acc.f[i][j] + bb);
    }
    STORE_ROWS(out_ig);
}

// k2: LC_t = leaky(bn1(LC_raw)) in-place sec0; NE_raw = LC_t@WLC + bLC -> sec4; BN2 stats.
__global__ void __launch_bounds__(NTH, 2) k2(
    float* lcraw_inout, const float* __restrict__ WLC, const float* __restrict__ bLC,
    const float* __restrict__ g1, const float* __restrict__ be1, float* out_neraw) {
    __shared__ u64 As2[KC * ASTP];
    __shared__ float Bs[KC * HD];
    GEMM_VARS;
    BN_INIT(0, g1, be1);
    MAINLOOP_TRANS(lcraw_inout, lcraw_inout, WLC);
#pragma unroll
    for (int j = 0; j < 8; j++) {
        float bb = __ldg(&bLC[tx * 8 + j]);
#pragma unroll
        for (int i = 0; i < 8; i++) acc.f[i][j] += bb;
    }
    STORE_ROWS(out_neraw);
    STATS_EPILOG(2);
}

// k3: NE_t = leaky(bn2(NE_raw)) -> sec1; new_cell = base + ig*0.1*(NE_t@WLC + bLC)
//     -> sec4 (in place over NE_raw); BN3 stats.
__global__ void __launch_bounds__(NTH, 2) k3(
    float* neraw_nc, float* out_net, const float* __restrict__ WLC,
    const float* __restrict__ bLC, const float* __restrict__ base,
    const float* __restrict__ ig, const float* __restrict__ g2,
    const float* __restrict__ be2) {
    __shared__ u64 As2[KC * ASTP];
    __shared__ float Bs[KC * HD];
    GEMM_VARS;
    BN_INIT(2, g2, be2);
    MAINLOOP_TRANS(neraw_nc, out_net, WLC);
    {
        float bL[8];
#pragma unroll
        for (int j = 0; j < 8; j++) bL[j] = __ldg(&bLC[tx * 8 + j]);
#pragma unroll
        for (int i = 0; i < 8; i++) {
            int gr = row0 + ty * 8 + i;
            float4 b0 = *(const float4*)(base + gr * HD + tx * 8);
            float4 b1 = *(const float4*)(base + gr * HD + tx * 8 + 4);
            float4 i0 = *(const float4*)(ig + gr * HD + tx * 8);
            float4 i1 = *(const float4*)(ig + gr * HD + tx * 8 + 4);
            float bv[8] = {b0.x, b0.y, b0.z, b0.w, b1.x, b1.y, b1.z, b1.w};
            float iv[8] = {i0.x, i0.y, i0.z, i0.w, i1.x, i1.y, i1.z, i1.w};
#pragma unroll
            for (int j = 0; j < 8; j++)
                acc.f[i][j] = fmaf(iv[j] * 0.1f, acc.f[i][j] + bL[j], bv[j]);
        }
    }
    STORE_ROWS(neraw_nc);
    STATS_EPILOG(4);
}

// k4: C_t = leaky(bn3(new_cell)) -> sec2; p[b] = (LC_t+C_t+NE_t)@WP;
//     Pupil = sigmoid(C_t@Wo + bo) * (p + bP) -> sec3.
__global__ void __launch_bounds__(NTH, 2) k4(
    const float* __restrict__ ncell, float* out_ct,
    const float* __restrict__ lct, const float* __restrict__ net,
    const float* __restrict__ Wo, const float* __restrict__ bo,
    const float* __restrict__ WP, const float* __restrict__ bP,
    const float* __restrict__ g3, const float* __restrict__ be3,
    float* out_pupil) {
    __shared__ u64 As2[KC * ASTP];
    __shared__ float Bs[KC * HD];
    __shared__ float sWP[HD];
    __shared__ float p_s[BMT];
    GEMM_VARS;
    BN_INIT(4, g3, be3);
    sWP[tid] = WP[tid];
    if (tid < BMT) p_s[tid] = 0.0f;
    float pval = 0.0f;
    MAINLOOP_TP(ncell, out_ct, lct, net, Wo);
    atomicAdd(&p_s[lr], pval);
    __syncthreads();
    {
        float bP0 = __ldg(&bP[0]);
        float bol[8];
#pragma unroll
        for (int j = 0; j < 8; j++) bol[j] = __ldg(&bo[tx * 8 + j]);
#pragma unroll
        for (int i = 0; i < 8; i++) {
            float pr = p_s[ty * 8 + i] + bP0;
#pragma unroll
            for (int j = 0; j < 8; j++)
                acc.f[i][j] = sigm(acc.f[i][j] + bol[j]) * pr;
        }
    }
    STORE_ROWS(out_pupil);
}

// ---------------- launch ----------------

extern "C" void kernel_launch(void* const* d_in, const int* in_sizes, int n_in,
                              void* d_out, int out_size) {
    (void)in_sizes; (void)n_in; (void)out_size;
    const float* X    = (const float*)d_in[0];
    const float* pLC  = (const float*)d_in[1];
    const float* pC   = (const float*)d_in[2];
    const float* cell = (const float*)d_in[3];
    const float* Wx = (const float*)d_in[4];   const float* bx = (const float*)d_in[5];
    const float* Wh = (const float*)d_in[6];   const float* bh = (const float*)d_in[7];
    const float* WLC = (const float*)d_in[8];  const float* bLC = (const float*)d_in[9];
    const float* WC = (const float*)d_in[10];  const float* bC = (const float*)d_in[11];
    const float* WP = (const float*)d_in[12];  const float* bP = (const float*)d_in[13];
    const float* Wf = (const float*)d_in[14];  const float* bf = (const float*)d_in[15];
    const float* Wi = (const float*)d_in[16];  const float* bi = (const float*)d_in[17];
    const float* Wo = (const float*)d_in[18];  const float* bo = (const float*)d_in[19];
    const float* g1 = (const float*)d_in[20];  const float* be1 = (const float*)d_in[21];
    const float* g2 = (const float*)d_in[22];  const float* be2 = (const float*)d_in[23];
    const float* g3 = (const float*)d_in[24];  const float* be3 = (const float*)d_in[25];

    float* o = (float*)d_out;
    const size_t SEC = (size_t)BD * HD;
    float* sLC = o;            // LC_t   (holds LC_raw until k2)
    float* sNE = o + SEC;      // NE_t
    float* sCT = o + 2 * SEC;  // C_t    (holds base until k3 consumes it)
    float* sPU = o + 3 * SEC;  // Pupil  (holds igate until k3 consumes it)
    float* sNC = o + 4 * SEC;  // new_cell (holds NE_raw until k3 overwrites)

    dim3 blk(NTH);
    dim3 grd(BD / BMT);

    k0_prep<<<HD + 1, NTH>>>(Wx, bx, Wi, bi, WC, bC);
    k1a<<<grd, blk>>>(X, pLC, Wx, Wh, bx, bh, sLC);
    k1b<<<grd, blk>>>(pC, X, Wf, bf, cell, sCT);
    k1c<<<grd, blk>>>(X, sPU);
    k2<<<grd, blk>>>(sLC, WLC, bLC, g1, be1, sNC);
    k3<<<grd, blk>>>(sNC, sNE, WLC, bLC, sCT, sPU, g2, be2);
    k4<<<grd, blk>>>(sNC, sCT, sLC, sNE, Wo, bo, WP, bP, g3, be3, sPU);
}

// round 5
// speedup vs baseline: 1.4292x; 1.0000x over previous
#include <cuda_runtime.h>
#include <math.h>

// LCNECortexLSTM: B=65536, D=H=256.
// Round 3: packed fma.rn.f32x2 (FFMA2) compute core. A-values stored duplicated
// in shared ((a,a) pairs, read with one LDS.64 broadcast); B pairs come free
// from LDS.128 register adjacency. 32 FFMA2 per k-step instead of 64 FFMA.
//
// Pipeline (all intermediates live inside d_out's 5 output sections):
//   k0:  WxWi = Wx@Wi, WxWC = Wx@WC, fused biases; zero BN stat accumulators.
//   k1a: LC_raw = X@Wx + pLC@Wh + (bx+bh)            -> sec0, + BN1 stats
//   k1b: base   = sigmoid(pC@Wf+bf)*cell + X@WxWC+b  -> sec2
//   k1c: igate  = sigmoid(X@WxWi + b)                -> sec3
//   k2 : LC_t = leaky(bn1(LC_raw)) (in-place sec0), NE_raw = LC_t@WLC+bLC -> sec4, + BN2 stats
//   k3 : NE_t = leaky(bn2(NE_raw)) -> sec1, new_cell = base + ig*0.1*(NE_t@WLC+bLC) -> sec4, + BN3 stats
//   k4 : C_t = leaky(bn3(new_cell)) -> sec2, p[b]=(LC_t+C_t+NE_t)@WP,
//        Pupil = sigmoid(C_t@Wo+bo)*(p+bP) -> sec3

#define BD 65536
#define HD 256
#define BMT 64
#define KC 16
#define NTH 256
#define ASTP 65  // stride of duplicated-A shared tile, in 8-byte units

typedef unsigned long long u64;

__device__ float g_WxWi[HD * HD];
__device__ float g_WxWC[HD * HD];
__device__ float g_bxWi[HD];
__device__ float g_bxWC[HD];
__device__ float g_stats[6 * HD];  // [sum1,sq1,sum2,sq2,sum3,sq3] per column

__device__ __forceinline__ float sigm(float x) { return 1.0f / (1.0f + expf(-x)); }
__device__ __forceinline__ float lky(float x) { return x > 0.0f ? x : 0.1f * x; }

// pack one float into both lanes of a 64-bit register pair
__device__ __forceinline__ u64 dup2(float x) {
    u64 r;
    asm("mov.b64 %0, {%1, %1};" : "=l"(r) : "f"(x));
    return r;
}

__device__ __forceinline__ void ffma2(u64& d, u64 a, u64 b) {
    asm("fma.rn.f32x2 %0, %1, %2, %0;" : "+l"(d) : "l"(a), "l"(b));
}

// acc viewed either as 8x4 packed pairs (compute) or 8x8 floats (epilogue).
// f[i][2*jp+0] = lo lane of u[i][jp], f[i][2*jp+1] = hi lane.
union AccU {
    u64 u[8][4];
    float f[8][8];
};

// ---------------- common GEMM macros ----------------

#define GEMM_VARS                                                     \
    const int tid = threadIdx.x;                                      \
    const int tx = tid & 31, ty = tid >> 5;                           \
    const int row0 = blockIdx.x * BMT;                                \
    const int lr = tid >> 2;                                          \
    const int lk = (tid & 3) * 4;                                     \
    AccU acc;                                                         \
    _Pragma("unroll") for (int i_ = 0; i_ < 8; i_++)                  \
        _Pragma("unroll") for (int j_ = 0; j_ < 4; j_++)              \
            acc.u[i_][j_] = 0ULL;

#define LOAD_B(WPTR, KC0)                                                          \
    {                                                                              \
        _Pragma("unroll") for (int t_ = 0; t_ < 4; t_++) {                         \
            int idx_ = t_ * NTH + tid;                                             \
            int bk_ = idx_ >> 6;                                                   \
            int bc_ = (idx_ & 63) << 2;                                            \
            *(float4*)&Bs[bk_ * HD + bc_] =                                        \
                *(const float4*)((WPTR) + ((KC0) + bk_) * HD + bc_);               \
        }                                                                          \
    }

#define LOAD_A_PLAIN(APTR, KC0)                                                    \
    {                                                                              \
        float4 av_ = *(const float4*)((APTR) + (row0 + lr) * HD + (KC0) + lk);     \
        As2[(lk + 0) * ASTP + lr] = dup2(av_.x);                                   \
        As2[(lk + 1) * ASTP + lr] = dup2(av_.y);                                   \
        As2[(lk + 2) * ASTP + lr] = dup2(av_.z);                                   \
        As2[(lk + 3) * ASTP + lr] = dup2(av_.w);                                   \
    }

#define COMPUTE_CHUNK                                                              \
    {                                                                              \
        _Pragma("unroll") for (int kk = 0; kk < KC; kk++) {                        \
            u64 a64_[8];                                                           \
            _Pragma("unroll") for (int i_ = 0; i_ < 8; i_++)                       \
                a64_[i_] = As2[kk * ASTP + ty * 8 + i_];                           \
            ulonglong2 bb0_ = *(const ulonglong2*)&Bs[kk * HD + tx * 8];           \
            ulonglong2 bb1_ = *(const ulonglong2*)&Bs[kk * HD + tx * 8 + 4];       \
            u64 b64_[4] = {bb0_.x, bb0_.y, bb1_.x, bb1_.y};                        \
            _Pragma("unroll") for (int i_ = 0; i_ < 8; i_++) {                     \
                _Pragma("unroll") for (int j_ = 0; j_ < 4; j_++)                   \
                    ffma2(acc.u[i_][j_], a64_[i_], b64_[j_]);                      \
            }                                                                      \
        }                                                                          \
    }

#define MAINLOOP_PLAIN(APTR, WPTR)                     \
    for (int kc0 = 0; kc0 < HD; kc0 += KC) {           \
        __syncthreads();                               \
        LOAD_A_PLAIN(APTR, kc0);                       \
        LOAD_B(WPTR, kc0);                             \
        __syncthreads();                               \
        COMPUTE_CHUNK;                                 \
    }

// BN-transform-on-load: y = leaky(x*scale[k]+shift[k]) applied while loading A;
// transformed values written to OUTPTR (each element loaded exactly once since
// the block covers the full N=256 width).
#define LOAD_A_TRANS(APTR, OUTPTR, KC0)                                            \
    {                                                                              \
        int aoff_ = (row0 + lr) * HD + (KC0) + lk;                                 \
        float4 av_ = *(const float4*)((APTR) + aoff_);                             \
        float4 tv_;                                                                \
        tv_.x = lky(fmaf(av_.x, sScale[(KC0) + lk + 0], sShift[(KC0) + lk + 0]));  \
        tv_.y = lky(fmaf(av_.y, sScale[(KC0) + lk + 1], sShift[(KC0) + lk + 1]));  \
        tv_.z = lky(fmaf(av_.z, sScale[(KC0) + lk + 2], sShift[(KC0) + lk + 2]));  \
        tv_.w = lky(fmaf(av_.w, sScale[(KC0) + lk + 3], sShift[(KC0) + lk + 3]));  \
        *(float4*)((OUTPTR) + aoff_) = tv_;                                        \
        As2[(lk + 0) * ASTP + lr] = dup2(tv_.x);                                   \
        As2[(lk + 1) * ASTP + lr] = dup2(tv_.y);                                   \
        As2[(lk + 2) * ASTP + lr] = dup2(tv_.z);                                   \
        As2[(lk + 3) * ASTP + lr] = dup2(tv_.w);                                   \
    }

#define MAINLOOP_TRANS(APTR, OUTPTR, WPTR)             \
    for (int kc0 = 0; kc0 < HD; kc0 += KC) {           \
        __syncthreads();                               \
        LOAD_A_TRANS(APTR, OUTPTR, kc0);               \
        LOAD_B(WPTR, kc0);                             \
        __syncthreads();                               \
        COMPUTE_CHUNK;                                 \
    }

// As K4's loader, plus accumulation of the Pupil GEMV partial.
#define LOAD_A_TP(APTR, OUTPTR, LCP, NEP, KC0)                                     \
    {                                                                              \
        int aoff_ = (row0 + lr) * HD + (KC0) + lk;                                 \
        float4 av_ = *(const float4*)((APTR) + aoff_);                             \
        float4 tv_;                                                                \
        tv_.x = lky(fmaf(av_.x, sScale[(KC0) + lk + 0], sShift[(KC0) + lk + 0]));  \
        tv_.y = lky(fmaf(av_.y, sScale[(KC0) + lk + 1], sShift[(KC0) + lk + 1]));  \
        tv_.z = lky(fmaf(av_.z, sScale[(KC0) + lk + 2], sShift[(KC0) + lk + 2]));  \
        tv_.w = lky(fmaf(av_.w, sScale[(KC0) + lk + 3], sShift[(KC0) + lk + 3]));  \
        *(float4*)((OUTPTR) + aoff_) = tv_;                                        \
        float4 lv_ = *(const float4*)((LCP) + aoff_);                              \
        float4 nv_ = *(const float4*)((NEP) + aoff_);                              \
        pval = fmaf(tv_.x + lv_.x + nv_.x, sWP[(KC0) + lk + 0], pval);             \
        pval = fmaf(tv_.y + lv_.y + nv_.y, sWP[(KC0) + lk + 1], pval);             \
        pval = fmaf(tv_.z + lv_.z + nv_.z, sWP[(KC0) + lk + 2], pval);             \
        pval = fmaf(tv_.w + lv_.w + nv_.w, sWP[(KC0) + lk + 3], pval);             \
        As2[(lk + 0) * ASTP + lr] = dup2(tv_.x);                                   \
        As2[(lk + 1) * ASTP + lr] = dup2(tv_.y);                                   \
        As2[(lk + 2) * ASTP + lr] = dup2(tv_.z);                                   \
        As2[(lk + 3) * ASTP + lr] = dup2(tv_.w);                                   \
    }

#define MAINLOOP_TP(APTR, OUTPTR, LCP, NEP, WPTR)      \
    for (int kc0 = 0; kc0 < HD; kc0 += KC) {           \
        __syncthreads();                               \
        LOAD_A_TP(APTR, OUTPTR, LCP, NEP, kc0);        \
        LOAD_B(WPTR, kc0);                             \
        __syncthreads();                               \
        COMPUTE_CHUNK;                                 \
    }

// Column sum / sumsq of the final values held in acc, block-reduced in smem
// (reusing Bs), then one atomicAdd per column per block.
#define STATS_EPILOG(SIDX)                                                          \
    {                                                                               \
        __syncthreads();                                                            \
        float* rsum_ = Bs;                                                          \
        float* rsq_ = Bs + 8 * HD;                                                  \
        _Pragma("unroll") for (int j_ = 0; j_ < 8; j_++) {                          \
            float s_ = 0.0f, q_ = 0.0f;                                             \
            _Pragma("unroll") for (int i_ = 0; i_ < 8; i_++) {                      \
                float v_ = acc.f[i_][j_];                                           \
                s_ += v_;                                                           \
                q_ = fmaf(v_, v_, q_);                                              \
            }                                                                       \
            rsum_[ty * HD + tx * 8 + j_] = s_;                                      \
            rsq_[ty * HD + tx * 8 + j_] = q_;                                       \
        }                                                                           \
        __syncthreads();                                                            \
        if (ty == 0) {                                                              \
            _Pragma("unroll") for (int j_ = 0; j_ < 8; j_++) {                      \
                int c_ = tx * 8 + j_;                                               \
                float S_ = 0.0f, Q_ = 0.0f;                                         \
                _Pragma("unroll") for (int t_ = 0; t_ < 8; t_++) {                  \
                    S_ += rsum_[t_ * HD + c_];                                      \
                    Q_ += rsq_[t_ * HD + c_];                                       \
                }                                                                   \
                atomicAdd(&g_stats[(SIDX)*HD + c_], S_);                            \
                atomicAdd(&g_stats[((SIDX) + 1) * HD + c_], Q_);                    \
            }                                                                       \
        }                                                                           \
    }

// Compute per-column BN scale/shift from accumulated stats (biased variance).
#define BN_INIT(SIDX, GAMMA, BETA)                                    \
    __shared__ float sScale[HD];                                      \
    __shared__ float sShift[HD];                                      \
    {                                                                 \
        int h_ = tid;                                                 \
        float m_ = g_stats[(SIDX)*HD + h_] * (1.0f / (float)BD);      \
        float e2_ = g_stats[((SIDX) + 1) * HD + h_] * (1.0f / (float)BD); \
        float rs_ = rsqrtf(e2_ - m_ * m_ + 1e-5f);                    \
        float sc_ = rs_ * (GAMMA)[h_];                                \
        sScale[h_] = sc_;                                             \
        sShift[h_] = (BETA)[h_] - m_ * sc_;                           \
    }

#define STORE_ROWS(OUTPTR)                                                    \
    _Pragma("unroll") for (int i_ = 0; i_ < 8; i_++) {                        \
        int gr_ = row0 + ty * 8 + i_;                                         \
        float4 v0_ = {acc.f[i_][0], acc.f[i_][1], acc.f[i_][2], acc.f[i_][3]};\
        float4 v1_ = {acc.f[i_][4], acc.f[i_][5], acc.f[i_][6], acc.f[i_][7]};\
        *(float4*)((OUTPTR) + gr_ * HD + tx * 8) = v0_;                       \
        *(float4*)((OUTPTR) + gr_ * HD + tx * 8 + 4) = v1_;                   \
    }

// ---------------- kernels ----------------

// k0: combined weights WxWi = Wx@Wi, WxWC = Wx@WC; fused biases; zero stats.
__global__ void __launch_bounds__(NTH) k0_prep(
    const float* __restrict__ Wx, const float* __restrict__ bx,
    const float* __restrict__ Wi, const float* __restrict__ bi,
    const float* __restrict__ WC, const float* __restrict__ bC) {
    int h = threadIdx.x;
    if (blockIdx.x < HD) {
        __shared__ float sA[HD];
        sA[h] = Wx[blockIdx.x * HD + h];
        __syncthreads();
        float aI = 0.0f, aC = 0.0f;
#pragma unroll 4
        for (int k = 0; k < HD; k++) {
            float a = sA[k];
            aI = fmaf(a, Wi[k * HD + h], aI);
            aC = fmaf(a, WC[k * HD + h], aC);
        }
        g_WxWi[blockIdx.x * HD + h] = aI;
        g_WxWC[blockIdx.x * HD + h] = aC;
    } else {
        float aI = bi[h], aC = bC[h];
        for (int k = 0; k < HD; k++) {
            float a = bx[k];
            aI = fmaf(a, Wi[k * HD + h], aI);
            aC = fmaf(a, WC[k * HD + h], aC);
        }
        g_bxWi[h] = aI;
        g_bxWC[h] = aC;
#pragma unroll
        for (int s = 0; s < 6; s++) g_stats[s * HD + h] = 0.0f;
    }
}

// k1a: LC_raw = X@Wx + pLC@Wh + (bx+bh) -> sec0, + BN1 stats.
__global__ void __launch_bounds__(NTH, 2) k1a(
    const float* __restrict__ X, const float* __restrict__ pLC,
    const float* __restrict__ Wx, const float* __restrict__ Wh,
    const float* __restrict__ bx, const float* __restrict__ bh,
    float* out_lcraw) {
    __shared__ u64 As2[KC * ASTP];
    __shared__ float Bs[KC * HD];
    GEMM_VARS;
    MAINLOOP_PLAIN(X, Wx);
    MAINLOOP_PLAIN(pLC, Wh);
#pragma unroll
    for (int j = 0; j < 8; j++) {
        int c = tx * 8 + j;
        float bb = __ldg(&bx[c]) + __ldg(&bh[c]);
#pragma unroll
        for (int i = 0; i < 8; i++) acc.f[i][j] += bb;
    }
    STORE_ROWS(out_lcraw);
    STATS_EPILOG(0);
}

// k1b: base = sigmoid(pC@Wf + bf)*cell + X@WxWC + bxWC -> sec2.
__global__ void __launch_bounds__(NTH, 2) k1b(
    const float* __restrict__ pC, const float* __restrict__ X,
    const float* __restrict__ Wf, const float* __restrict__ bf,
    const float* __restrict__ cell, float* out_base) {
    __shared__ u64 As2[KC * ASTP];
    __shared__ float Bs[KC * HD];
    GEMM_VARS;
    MAINLOOP_PLAIN(pC, Wf);
    // mid-transform: acc <- sigmoid(acc+bf)*cell
    {
        float bfl[8];
#pragma unroll
        for (int j = 0; j < 8; j++) bfl[j] = __ldg(&bf[tx * 8 + j]);
#pragma unroll
        for (int i = 0; i < 8; i++) {
            int gr = row0 + ty * 8 + i;
            float4 c0 = *(const float4*)(cell + gr * HD + tx * 8);
            float4 c1 = *(const float4*)(cell + gr * HD + tx * 8 + 4);
            float cv[8] = {c0.x, c0.y, c0.z, c0.w, c1.x, c1.y, c1.z, c1.w};
#pragma unroll
            for (int j = 0; j < 8; j++)
                acc.f[i][j] = sigm(acc.f[i][j] + bfl[j]) * cv[j];
        }
    }
    MAINLOOP_PLAIN(X, g_WxWC);
#pragma unroll
    for (int j = 0; j < 8; j++) {
        float bb = g_bxWC[tx * 8 + j];
#pragma unroll
        for (int i = 0; i < 8; i++) acc.f[i][j] += bb;
    }
    STORE_ROWS(out_base);
}

// k1c: igate = sigmoid(X@WxWi + bxWi) -> sec3.
__global__ void __launch_bounds__(NTH, 2) k1c(const float* __restrict__ X, float* out_ig) {
    __shared__ u64 As2[KC * ASTP];
    __shared__ float Bs[KC * HD];
    GEMM_VARS;
    MAINLOOP_PLAIN(X, g_WxWi);
#pragma unroll
    for (int j = 0; j < 8; j++) {
        float bb = g_bxWi[tx * 8 + j];
#pragma unroll
        for (int i = 0; i < 8; i++) acc.f[i][j] = sigm(acc.f[i][j] + bb);
    }
    STORE_ROWS(out_ig);
}

// k2: LC_t = leaky(bn1(LC_raw)) in-place sec0; NE_raw = LC_t@WLC + bLC -> sec4; BN2 stats.
__global__ void __launch_bounds__(NTH, 2) k2(
    float* lcraw_inout, const float* __restrict__ WLC, const float* __restrict__ bLC,
    const float* __restrict__ g1, const float* __restrict__ be1, float* out_neraw) {
    __shared__ u64 As2[KC * ASTP];
    __shared__ float Bs[KC * HD];
    GEMM_VARS;
    BN_INIT(0, g1, be1);
    MAINLOOP_TRANS(lcraw_inout, lcraw_inout, WLC);
#pragma unroll
    for (int j = 0; j < 8; j++) {
        float bb = __ldg(&bLC[tx * 8 + j]);
#pragma unroll
        for (int i = 0; i < 8; i++) acc.f[i][j] += bb;
    }
    STORE_ROWS(out_neraw);
    STATS_EPILOG(2);
}

// k3: NE_t = leaky(bn2(NE_raw)) -> sec1; new_cell = base + ig*0.1*(NE_t@WLC + bLC)
//     -> sec4 (in place over NE_raw); BN3 stats.
__global__ void __launch_bounds__(NTH, 2) k3(
    float* neraw_nc, float* out_net, const float* __restrict__ WLC,
    const float* __restrict__ bLC, const float* __restrict__ base,
    const float* __restrict__ ig, const float* __restrict__ g2,
    const float* __restrict__ be2) {
    __shared__ u64 As2[KC * ASTP];
    __shared__ float Bs[KC * HD];
    GEMM_VARS;
    BN_INIT(2, g2, be2);
    MAINLOOP_TRANS(neraw_nc, out_net, WLC);
    {
        float bL[8];
#pragma unroll
        for (int j = 0; j < 8; j++) bL[j] = __ldg(&bLC[tx * 8 + j]);
#pragma unroll
        for (int i = 0; i < 8; i++) {
            int gr = row0 + ty * 8 + i;
            float4 b0 = *(const float4*)(base + gr * HD + tx * 8);
            float4 b1 = *(const float4*)(base + gr * HD + tx * 8 + 4);
            float4 i0 = *(const float4*)(ig + gr * HD + tx * 8);
            float4 i1 = *(const float4*)(ig + gr * HD + tx * 8 + 4);
            float bv[8] = {b0.x, b0.y, b0.z, b0.w, b1.x, b1.y, b1.z, b1.w};
            float iv[8] = {i0.x, i0.y, i0.z, i0.w, i1.x, i1.y, i1.z, i1.w};
#pragma unroll
            for (int j = 0; j < 8; j++)
                acc.f[i][j] = fmaf(iv[j] * 0.1f, acc.f[i][j] + bL[j], bv[j]);
        }
    }
    STORE_ROWS(neraw_nc);
    STATS_EPILOG(4);
}

// k4: C_t = leaky(bn3(new_cell)) -> sec2; p[b] = (LC_t+C_t+NE_t)@WP;
//     Pupil = sigmoid(C_t@Wo + bo) * (p + bP) -> sec3.
__global__ void __launch_bounds__(NTH, 2) k4(
    const float* __restrict__ ncell, float* out_ct,
    const float* __restrict__ lct, const float* __restrict__ net,
    const float* __restrict__ Wo, const float* __restrict__ bo,
    const float* __restrict__ WP, const float* __restrict__ bP,
    const float* __restrict__ g3, const float* __restrict__ be3,
    float* out_pupil) {
    __shared__ u64 As2[KC * ASTP];
    __shared__ float Bs[KC * HD];
    __shared__ float sWP[HD];
    __shared__ float p_s[BMT];
    GEMM_VARS;
    BN_INIT(4, g3, be3);
    sWP[tid] = WP[tid];
    if (tid < BMT) p_s[tid] = 0.0f;
    float pval = 0.0f;
    MAINLOOP_TP(ncell, out_ct, lct, net, Wo);
    atomicAdd(&p_s[lr], pval);
    __syncthreads();
    {
        float bP0 = __ldg(&bP[0]);
        float bol[8];
#pragma unroll
        for (int j = 0; j < 8; j++) bol[j] = __ldg(&bo[tx * 8 + j]);
#pragma unroll
        for (int i = 0; i < 8; i++) {
            float pr = p_s[ty * 8 + i] + bP0;
#pragma unroll
            for (int j = 0; j < 8; j++)
                acc.f[i][j] = sigm(acc.f[i][j] + bol[j]) * pr;
        }
    }
    STORE_ROWS(out_pupil);
}

// ---------------- launch ----------------

extern "C" void kernel_launch(void* const* d_in, const int* in_sizes, int n_in,
                              void* d_out, int out_size) {
    (void)in_sizes; (void)n_in; (void)out_size;
    const float* X    = (const float*)d_in[0];
    const float* pLC  = (const float*)d_in[1];
    const float* pC   = (const float*)d_in[2];
    const float* cell = (const float*)d_in[3];
    const float* Wx = (const float*)d_in[4];   const float* bx = (const float*)d_in[5];
    const float* Wh = (const float*)d_in[6];   const float* bh = (const float*)d_in[7];
    const float* WLC = (const float*)d_in[8];  const float* bLC = (const float*)d_in[9];
    const float* WC = (const float*)d_in[10];  const float* bC = (const float*)d_in[11];
    const float* WP = (const float*)d_in[12];  const float* bP = (const float*)d_in[13];
    const float* Wf = (const float*)d_in[14];  const float* bf = (const float*)d_in[15];
    const float* Wi = (const float*)d_in[16];  const float* bi = (const float*)d_in[17];
    const float* Wo = (const float*)d_in[18];  const float* bo = (const float*)d_in[19];
    const float* g1 = (const float*)d_in[20];  const float* be1 = (const float*)d_in[21];
    const float* g2 = (const float*)d_in[22];  const float* be2 = (const float*)d_in[23];
    const float* g3 = (const float*)d_in[24];  const float* be3 = (const float*)d_in[25];

    float* o = (float*)d_out;
    const size_t SEC = (size_t)BD * HD;
    float* sLC = o;            // LC_t   (holds LC_raw until k2)
    float* sNE = o + SEC;      // NE_t
    float* sCT = o + 2 * SEC;  // C_t    (holds base until k3 consumes it)
    float* sPU = o + 3 * SEC;  // Pupil  (holds igate until k3 consumes it)
    float* sNC = o + 4 * SEC;  // new_cell (holds NE_raw until k3 overwrites)

    dim3 blk(NTH);
    dim3 grd(BD / BMT);

    k0_prep<<<HD + 1, NTH>>>(Wx, bx, Wi, bi, WC, bC);
    k1a<<<grd, blk>>>(X, pLC, Wx, Wh, bx, bh, sLC);
    k1b<<<grd, blk>>>(pC, X, Wf, bf, cell, sCT);
    k1c<<<grd, blk>>>(X, sPU);
    k2<<<grd, blk>>>(sLC, WLC, bLC, g1, be1, sNC);
    k3<<<grd, blk>>>(sNC, sNE, WLC, bLC, sCT, sPU, g2, be2);
    k4<<<grd, blk>>>(sNC, sCT, sLC, sNE, Wo, bo, WP, bP, g3, be3, sPU);
}

// round 9
// speedup vs baseline: 1.8109x; 1.2670x over previous
#include <cuda_runtime.h>
#include <cuda_bf16.h>
#include <math.h>
#include <stdint.h>

// LCNECortexLSTM B=65536, D=H=256 — mma.sync (HMMA bf16) split-precision pipeline.
// D_fp32 = Ahi@Bhi + Ahi@Blo + Alo@Bhi. CTA tile 128x256, K chunks of 64.
// 8 warps = 2(M) x 4(N), warp tile 64x64, m16n8k16 fragments via ldmatrix.
// Kernels: k0(prep) kW(weight images) k1a k1b k1c k2 k3 k4.

#define BD 65536
#define HD 256
#define MT 128
#define NTH 256

#define OFF_ALO 16384
#define OFF_BHI 32768
#define OFF_BLO 65536
#define OFF_SCALE 98304
#define OFF_SHIFT 99328
#define OFF_WP 100352
#define OFF_PS 101376
#define SMEM_REQ 102912

// weight images: [mat][hi/lo], transposed [N][K], chunked 4x(256 rows x 64 k),
// 128B rows with XOR-16B swizzle. mats: 0=Wx 1=Wh 2=Wf 3=WxWC 4=WxWi 5=WLC 6=Wo
__device__ __nv_bfloat16 g_Wimg[7][2][HD * HD];
__device__ float g_WxWi[HD * HD];
__device__ float g_WxWC[HD * HD];
__device__ float g_bxWi[HD];
__device__ float g_bxWC[HD];
__device__ float g_stats[6 * HD];

__device__ __forceinline__ float sigm(float x) { return 1.0f / (1.0f + expf(-x)); }
__device__ __forceinline__ float lky(float x) { return x > 0.0f ? x : 0.1f * x; }

__device__ __forceinline__ uint32_t smem_to_u32(const void* p) {
    uint32_t a;
    asm("{ .reg .u64 t; cvta.to.shared.u64 t, %1; cvt.u32.u64 %0, t; }" : "=r"(a) : "l"(p));
    return a;
}

__device__ __forceinline__ void ldsm_x4(uint32_t* r, uint32_t addr) {
    asm volatile("ldmatrix.sync.aligned.m8n8.x4.shared.b16 {%0,%1,%2,%3}, [%4];"
        : "=r"(r[0]), "=r"(r[1]), "=r"(r[2]), "=r"(r[3]) : "r"(addr));
}
__device__ __forceinline__ void ldsm_x2(uint32_t* r, uint32_t addr) {
    asm volatile("ldmatrix.sync.aligned.m8n8.x2.shared.b16 {%0,%1}, [%2];"
        : "=r"(r[0]), "=r"(r[1]) : "r"(addr));
}
__device__ __forceinline__ void mma_bf16(float* c, const uint32_t* a, const uint32_t* b) {
    asm volatile("mma.sync.aligned.m16n8k16.row.col.f32.bf16.bf16.f32 "
        "{%0,%1,%2,%3}, {%4,%5,%6,%7}, {%8,%9}, {%0,%1,%2,%3};"
        : "+f"(c[0]), "+f"(c[1]), "+f"(c[2]), "+f"(c[3])
        : "r"(a[0]), "r"(a[1]), "r"(a[2]), "r"(a[3]), "r"(b[0]), "r"(b[1]));
}

__device__ __forceinline__ uint32_t pack_split(float a, float b, uint32_t& lo) {
    __nv_bfloat162 h = __floats2bfloat162_rn(a, b);
    __nv_bfloat162 l = __floats2bfloat162_rn(a - __low2float(h), b - __high2float(h));
    lo = *reinterpret_cast<uint32_t*>(&l);
    return *reinterpret_cast<uint32_t*>(&h);
}

// linear copy of one pre-swizzled 32KB hi + 32KB lo weight chunk into smem
__device__ __forceinline__ void load_B(char* dh_, char* dl_,
                                       const __nv_bfloat16* Whi, const __nv_bfloat16* Wlo,
                                       int chunk, int tid) {
    const uint4* sh = (const uint4*)(Whi + chunk * 16384);
    const uint4* sl = (const uint4*)(Wlo + chunk * 16384);
    uint4* dh = (uint4*)dh_;
    uint4* dl = (uint4*)dl_;
#pragma unroll
    for (int i = 0; i < 8; i++) {
        dh[i * NTH + tid] = sh[i * NTH + tid];
        dl[i * NTH + tid] = sl[i * NTH + tid];
    }
}

// ---------------- kernel body macros ----------------

#define GEMM_PROLOG                                                           \
    extern __shared__ char dsm_[];                                            \
    char* smem = (char*)(((uintptr_t)dsm_ + 1023) & ~(uintptr_t)1023);        \
    const int tid = threadIdx.x, wid = tid >> 5, lane = tid & 31;             \
    const int wm = wid & 1, wn = wid >> 1;                                    \
    const int row0 = blockIdx.x * MT;                                         \
    const uint32_t su = smem_to_u32(smem);                                    \
    char* sAhi = smem; char* sAlo = smem + OFF_ALO;                           \
    char* sBhi = smem + OFF_BHI; char* sBlo = smem + OFF_BLO;                 \
    const uint32_t uAhi = su, uAlo = su + OFF_ALO;                            \
    const uint32_t uBhi = su + OFF_BHI, uBlo = su + OFF_BLO;                  \
    float* sScale = (float*)(smem + OFF_SCALE);                               \
    float* sShift = (float*)(smem + OFF_SHIFT);                               \
    (void)sScale; (void)sShift; (void)sAlo; (void)sBlo;                       \
    float acc[4][8][4];                                                       \
    _Pragma("unroll") for (int i_ = 0; i_ < 4; i_++)                          \
        _Pragma("unroll") for (int j_ = 0; j_ < 8; j_++)                      \
            _Pragma("unroll") for (int q_ = 0; q_ < 4; q_++)                  \
                acc[i_][j_][q_] = 0.0f;

#define COMPUTE_CHUNK                                                         \
    __syncthreads();                                                          \
    _Pragma("unroll") for (int ks = 0; ks < 4; ks++) {                        \
        uint32_t ah[4][4], al[4][4];                                          \
        _Pragma("unroll") for (int mi = 0; mi < 4; mi++) {                    \
            int r = wm * 64 + mi * 16 + (lane & 15);                          \
            int kb = ks * 32 + ((lane & 16) ? 16 : 0);                        \
            uint32_t sw = (uint32_t)r * 128 + (kb ^ ((r & 7) << 4));          \
            ldsm_x4(ah[mi], uAhi + sw);                                       \
            ldsm_x4(al[mi], uAlo + sw);                                       \
        }                                                                     \
        _Pragma("unroll") for (int ni = 0; ni < 8; ni++) {                    \
            int l = lane & 15;                                                \
            int rn = wn * 64 + ni * 8 + (l & 7);                              \
            int kb = ks * 32 + ((l & 8) ? 16 : 0);                            \
            uint32_t sw = (uint32_t)rn * 128 + (kb ^ ((rn & 7) << 4));        \
            uint32_t bh2[2], bl2[2];                                          \
            ldsm_x2(bh2, uBhi + sw);                                          \
            ldsm_x2(bl2, uBlo + sw);                                          \
            _Pragma("unroll") for (int mi = 0; mi < 4; mi++) {                \
                mma_bf16(acc[mi][ni], ah[mi], bh2);                           \
                mma_bf16(acc[mi][ni], ah[mi], bl2);                           \
                mma_bf16(acc[mi][ni], al[mi], bh2);                           \
            }                                                                 \
        }                                                                     \
    }

#define SPLIT_STORE(av, r, cc)                                                \
    {                                                                         \
        uint2 h2, l2;                                                         \
        h2.x = pack_split((av).x, (av).y, l2.x);                              \
        h2.y = pack_split((av).z, (av).w, l2.y);                              \
        uint32_t off = (uint32_t)(r) * 128 + (((cc) * 2) ^ (((r) & 7) << 4)); \
        *(uint2*)(sAhi + off) = h2;                                           \
        *(uint2*)(sAlo + off) = l2;                                           \
    }

#define A_LOAD_PLAIN(SRC, KB)                                                 \
    {                                                                         \
        const int cr = tid >> 4, cc = (tid & 15) * 4;                         \
        _Pragma("unroll") for (int ii = 0; ii < 8; ii++) {                    \
            const int r = cr + ii * 16;                                       \
            float4 av = *(const float4*)((SRC) + (size_t)(row0 + r) * HD + (KB) + cc); \
            SPLIT_STORE(av, r, cc);                                           \
        }                                                                     \
    }

#define A_LOAD_TRANS(SRC, OUT, KB)                                            \
    {                                                                         \
        const int cr = tid >> 4, cc = (tid & 15) * 4;                         \
        float4 sc = *(float4*)&sScale[(KB) + cc];                             \
        float4 sh = *(float4*)&sShift[(KB) + cc];                             \
        _Pragma("unroll") for (int ii = 0; ii < 8; ii++) {                    \
            const int r = cr + ii * 16;                                       \
            size_t gx = (size_t)(row0 + r) * HD + (KB) + cc;                  \
            float4 av = *(const float4*)((SRC) + gx);                         \
            av.x = lky(fmaf(av.x, sc.x, sh.x));                               \
            av.y = lky(fmaf(av.y, sc.y, sh.y));                               \
            av.z = lky(fmaf(av.z, sc.z, sh.z));                               \
            av.w = lky(fmaf(av.w, sc.w, sh.w));                               \
            *(float4*)((OUT) + gx) = av;                                      \
            SPLIT_STORE(av, r, cc);                                           \
        }                                                                     \
    }

#define A_LOAD_TP(SRC, OUT, LCP, NEP, KB)                                     \
    {                                                                         \
        const int cr = tid >> 4, cc = (tid & 15) * 4;                         \
        float4 sc = *(float4*)&sScale[(KB) + cc];                             \
        float4 sh = *(float4*)&sShift[(KB) + cc];                             \
        float4 wp = *(float4*)&sWP[(KB) + cc];                                \
        _Pragma("unroll") for (int ii = 0; ii < 8; ii++) {                    \
            const int r = cr + ii * 16;                                       \
            size_t gx = (size_t)(row0 + r) * HD + (KB) + cc;                  \
            float4 av = *(const float4*)((SRC) + gx);                         \
            av.x = lky(fmaf(av.x, sc.x, sh.x));                               \
            av.y = lky(fmaf(av.y, sc.y, sh.y));                               \
            av.z = lky(fmaf(av.z, sc.z, sh.z));                               \
            av.w = lky(fmaf(av.w, sc.w, sh.w));                               \
            *(float4*)((OUT) + gx) = av;                                      \
            float4 lv = *(const float4*)((LCP) + gx);                         \
            float4 nv = *(const float4*)((NEP) + gx);                         \
            pv[ii] = fmaf(av.x + lv.x + nv.x, wp.x, pv[ii]);                  \
            pv[ii] = fmaf(av.y + lv.y + nv.y, wp.y, pv[ii]);                  \
            pv[ii] = fmaf(av.z + lv.z + nv.z, wp.z, pv[ii]);                  \
            pv[ii] = fmaf(av.w + lv.w + nv.w, wp.w, pv[ii]);                  \
            SPLIT_STORE(av, r, cc);                                           \
        }                                                                     \
    }

// epilogue iteration: rr = global row, cb = column (pair base), vx/vy = values.
#define EPI_BEGIN                                                             \
    _Pragma("unroll") for (int mi = 0; mi < 4; mi++) {                        \
        _Pragma("unroll") for (int h = 0; h < 2; h++) {                       \
            const int rr = row0 + wm * 64 + mi * 16 + (lane >> 2) + h * 8;    \
            _Pragma("unroll") for (int ni = 0; ni < 8; ni++) {                \
                const int cb = wn * 64 + ni * 8 + (lane & 3) * 2;             \
                float vx = acc[mi][ni][h * 2], vy = acc[mi][ni][h * 2 + 1];   \
                (void)cb;

#define EPI_END_STORE(OUT)                                                    \
                *(float2*)((OUT) + (size_t)rr * HD + cb) = make_float2(vx, vy); \
            } } }

#define EPI_END_ACC                                                           \
                acc[mi][ni][h * 2] = vx; acc[mi][ni][h * 2 + 1] = vy;         \
            } } }

#define STATS_DECL                                                            \
    float ssum[8][2], ssq[8][2];                                              \
    _Pragma("unroll") for (int i_ = 0; i_ < 8; i_++) {                        \
        ssum[i_][0] = ssum[i_][1] = 0.0f; ssq[i_][0] = ssq[i_][1] = 0.0f; }

#define STATS_ACC                                                             \
    ssum[ni][0] += vx; ssq[ni][0] += vx * vx;                                 \
    ssum[ni][1] += vy; ssq[ni][1] += vy * vy;

#define STATS_REDUCE(SIDX)                                                    \
    _Pragma("unroll") for (int ni = 0; ni < 8; ni++) {                        \
        _Pragma("unroll") for (int c2 = 0; c2 < 2; c2++) {                    \
            float s_ = ssum[ni][c2], q_ = ssq[ni][c2];                        \
            s_ += __shfl_xor_sync(~0u, s_, 4);  q_ += __shfl_xor_sync(~0u, q_, 4);  \
            s_ += __shfl_xor_sync(~0u, s_, 8);  q_ += __shfl_xor_sync(~0u, q_, 8);  \
            s_ += __shfl_xor_sync(~0u, s_, 16); q_ += __shfl_xor_sync(~0u, q_, 16); \
            if (lane < 4) {                                                   \
                int col = wn * 64 + ni * 8 + lane * 2 + c2;                   \
                atomicAdd(&g_stats[(SIDX) * HD + col], s_);                   \
                atomicAdd(&g_stats[((SIDX) + 1) * HD + col], q_);             \
            } } }

#define BN_PREP(SIDX, G, B)                                                   \
    {                                                                         \
        float m_ = g_stats[(SIDX) * HD + tid] * (1.0f / (float)BD);           \
        float e2_ = g_stats[((SIDX) + 1) * HD + tid] * (1.0f / (float)BD);    \
        float rs_ = rsqrtf(e2_ - m_ * m_ + 1e-5f);                            \
        float sc_ = rs_ * (G)[tid];                                           \
        sScale[tid] = sc_;                                                    \
        sShift[tid] = (B)[tid] - m_ * sc_;                                    \
    }

// per-ni column-pair bias preload
#define BIAS8(DST, SRCP)                                                      \
    float2 DST[8];                                                            \
    _Pragma("unroll") for (int i_ = 0; i_ < 8; i_++)                          \
        DST[i_] = *(const float2*)((SRCP) + wn * 64 + i_ * 8 + (lane & 3) * 2);

// ---------------- prep kernels ----------------

__global__ void __launch_bounds__(NTH) k0_prep(
    const float* __restrict__ Wx, const float* __restrict__ bx,
    const float* __restrict__ Wi, const float* __restrict__ bi,
    const float* __restrict__ WC, const float* __restrict__ bC) {
    int h = threadIdx.x;
    if (blockIdx.x < HD) {
        __shared__ float sA[HD];
        sA[h] = Wx[blockIdx.x * HD + h];
        __syncthreads();
        float aI = 0.0f, aC = 0.0f;
#pragma unroll 4
        for (int k = 0; k < HD; k++) {
            float a = sA[k];
            aI = fmaf(a, Wi[k * HD + h], aI);
            aC = fmaf(a, WC[k * HD + h], aC);
        }
        g_WxWi[blockIdx.x * HD + h] = aI;
        g_WxWC[blockIdx.x * HD + h] = aC;
    } else {
        float aI = bi[h], aC = bC[h];
        for (int k = 0; k < HD; k++) {
            float a = bx[k];
            aI = fmaf(a, Wi[k * HD + h], aI);
            aC = fmaf(a, WC[k * HD + h], aC);
        }
        g_bxWi[h] = aI;
        g_bxWC[h] = aC;
#pragma unroll
        for (int s = 0; s < 6; s++) g_stats[s * HD + h] = 0.0f;
    }
}

// weights -> transposed [N][K] bf16 hi/lo, chunked by K=64, XOR-swizzled 128B rows
__global__ void __launch_bounds__(NTH) kW(
    const float* __restrict__ Wx, const float* __restrict__ Wh,
    const float* __restrict__ Wf, const float* __restrict__ WLC,
    const float* __restrict__ Wo) {
    int k = blockIdx.x, m = blockIdx.y, n = threadIdx.x;
    const float* src;
    switch (m) {
        case 0: src = Wx; break;
        case 1: src = Wh; break;
        case 2: src = Wf; break;
        case 3: src = g_WxWC; break;
        case 4: src = g_WxWi; break;
        case 5: src = WLC; break;
        default: src = Wo; break;
    }
    float val = src[k * HD + n];
    __nv_bfloat16 h = __float2bfloat16(val);
    __nv_bfloat16 l = __float2bfloat16(val - __bfloat162float(h));
    int chunk = k >> 6, kk = k & 63;
    uint32_t off = (uint32_t)chunk * 32768 + (uint32_t)n * 128 + ((kk * 2) ^ ((n & 7) << 4));
    *(__nv_bfloat16*)((char*)g_Wimg[m][0] + off) = h;
    *(__nv_bfloat16*)((char*)g_Wimg[m][1] + off) = l;
}

// ---------------- GEMM kernels ----------------

// k1a: LC_raw = X@Wx + pLC@Wh + (bx+bh) -> sec0; stats0
__global__ void __launch_bounds__(NTH) k1a(
    const float* __restrict__ X, const float* __restrict__ pLC,
    const float* __restrict__ bx, const float* __restrict__ bh_, float* out) {
    GEMM_PROLOG;
#pragma unroll 1
    for (int c = 0; c < 8; c++) {
        __syncthreads();
        const float* src = (c < 4) ? X : pLC;
        int mat = (c < 4) ? 0 : 1;
        int cc4 = c & 3;
        A_LOAD_PLAIN(src, cc4 * 64);
        load_B(sBhi, sBlo, g_Wimg[mat][0], g_Wimg[mat][1], cc4, tid);
        COMPUTE_CHUNK;
    }
    BIAS8(b1, bx); BIAS8(b2, bh_);
    STATS_DECL;
    EPI_BEGIN;
    vx += b1[ni].x + b2[ni].x;
    vy += b1[ni].y + b2[ni].y;
    STATS_ACC;
    EPI_END_STORE(out);
    STATS_REDUCE(0);
}

// k1b: base = sigmoid(pC@Wf+bf)*cell + X@WxWC + bxWC -> sec2 (one kernel, mid-transform)
__global__ void __launch_bounds__(NTH) k1b(
    const float* __restrict__ pC, const float* __restrict__ X,
    const float* __restrict__ bf_, const float* __restrict__ cell, float* out) {
    GEMM_PROLOG;
#pragma unroll 1
    for (int c = 0; c < 4; c++) {
        __syncthreads();
        A_LOAD_PLAIN(pC, c * 64);
        load_B(sBhi, sBlo, g_Wimg[2][0], g_Wimg[2][1], c, tid);
        COMPUTE_CHUNK;
    }
    {
        BIAS8(bfv, bf_);
        EPI_BEGIN;
        float2 cv = *(const float2*)(cell + (size_t)rr * HD + cb);
        vx = sigm(vx + bfv[ni].x) * cv.x;
        vy = sigm(vy + bfv[ni].y) * cv.y;
        EPI_END_ACC;
    }
#pragma unroll 1
    for (int c = 0; c < 4; c++) {
        __syncthreads();
        A_LOAD_PLAIN(X, c * 64);
        load_B(sBhi, sBlo, g_Wimg[3][0], g_Wimg[3][1], c, tid);
        COMPUTE_CHUNK;
    }
    BIAS8(bb, g_bxWC);
    EPI_BEGIN;
    vx += bb[ni].x;
    vy += bb[ni].y;
    EPI_END_STORE(out);
}

// k1c: igate = sigmoid(X@WxWi + bxWi) -> sec3
__global__ void __launch_bounds__(NTH) k1c(const float* __restrict__ X, float* out) {
    GEMM_PROLOG;
#pragma unroll 1
    for (int c = 0; c < 4; c++) {
        __syncthreads();
        A_LOAD_PLAIN(X, c * 64);
        load_B(sBhi, sBlo, g_Wimg[4][0], g_Wimg[4][1], c, tid);
        COMPUTE_CHUNK;
    }
    BIAS8(bb, g_bxWi);
    EPI_BEGIN;
    vx = sigm(vx + bb[ni].x);
    vy = sigm(vy + bb[ni].y);
    EPI_END_STORE(out);
}

// k2: LC_t = leaky(bn1(sec0)) in place; NE_raw = LC_t@WLC + bLC -> sec4; stats2
__global__ void __launch_bounds__(NTH) k2(
    float* lcio, const float* __restrict__ bLC,
    const float* __restrict__ g1, const float* __restrict__ be1, float* out) {
    GEMM_PROLOG;
    BN_PREP(0, g1, be1);
#pragma unroll 1
    for (int c = 0; c < 4; c++) {
        __syncthreads();
        A_LOAD_TRANS(lcio, lcio, c * 64);
        load_B(sBhi, sBlo, g_Wimg[5][0], g_Wimg[5][1], c, tid);
        COMPUTE_CHUNK;
    }
    BIAS8(bb, bLC);
    STATS_DECL;
    EPI_BEGIN;
    vx += bb[ni].x;
    vy += bb[ni].y;
    STATS_ACC;
    EPI_END_STORE(out);
    STATS_REDUCE(2);
}

// k3: NE_t = leaky(bn2(sec4)) -> sec1; new_cell = base + ig*0.1*(NE_t@WLC+bLC) -> sec4; stats4
__global__ void __launch_bounds__(NTH) k3(
    float* nc, float* out_net, const float* __restrict__ bLC,
    const float* __restrict__ base, const float* __restrict__ ig,
    const float* __restrict__ g2, const float* __restrict__ be2) {
    GEMM_PROLOG;
    BN_PREP(2, g2, be2);
#pragma unroll 1
    for (int c = 0; c < 4; c++) {
        __syncthreads();
        A_LOAD_TRANS(nc, out_net, c * 64);
        load_B(sBhi, sBlo, g_Wimg[5][0], g_Wimg[5][1], c, tid);
        COMPUTE_CHUNK;
    }
    BIAS8(bb, bLC);
    STATS_DECL;
    EPI_BEGIN;
    float2 bv = *(const float2*)(base + (size_t)rr * HD + cb);
    float2 iv = *(const float2*)(ig + (size_t)rr * HD + cb);
    vx = fmaf(iv.x * 0.1f, vx + bb[ni].x, bv.x);
    vy = fmaf(iv.y * 0.1f, vy + bb[ni].y, bv.y);
    STATS_ACC;
    EPI_END_STORE(nc);
    STATS_REDUCE(4);
}

// k4: C_t = leaky(bn3(sec4)) -> sec2; p = (LC_t+C_t+NE_t)@WP;
//     Pupil = sigmoid(C_t@Wo+bo)*(p+bP) -> sec3
__global__ void __launch_bounds__(NTH) k4(
    const float* __restrict__ ncell, float* out_ct,
    const float* __restrict__ lct, const float* __restrict__ net,
    const float* __restrict__ bo, const float* __restrict__ WP,
    const float* __restrict__ bP, const float* __restrict__ g3,
    const float* __restrict__ be3, float* out_pupil) {
    GEMM_PROLOG;
    BN_PREP(4, g3, be3);
    float* sWP = (float*)(smem + OFF_WP);
    float* p_s = (float*)(smem + OFF_PS);
    sWP[tid] = WP[tid];
    if (tid < MT) p_s[tid] = 0.0f;
    float pv[8];
#pragma unroll
    for (int i = 0; i < 8; i++) pv[i] = 0.0f;
#pragma unroll 1
    for (int c = 0; c < 4; c++) {
        __syncthreads();
        A_LOAD_TP(ncell, out_ct, lct, net, c * 64);
        load_B(sBhi, sBlo, g_Wimg[6][0], g_Wimg[6][1], c, tid);
        COMPUTE_CHUNK;
    }
    {
        const int crr = tid >> 4;
#pragma unroll
        for (int ii = 0; ii < 8; ii++) atomicAdd(&p_s[crr + ii * 16], pv[ii]);
    }
    __syncthreads();
    float bP0 = bP[0];
    BIAS8(bb, bo);
    EPI_BEGIN;
    float pr = p_s[rr - row0] + bP0;
    vx = sigm(vx + bb[ni].x) * pr;
    vy = sigm(vy + bb[ni].y) * pr;
    EPI_END_STORE(out_pupil);
}

// ---------------- launch ----------------

extern "C" void kernel_launch(void* const* d_in, const int* in_sizes, int n_in,
                              void* d_out, int out_size) {
    (void)in_sizes; (void)n_in; (void)out_size;
    const float* X    = (const float*)d_in[0];
    const float* pLC  = (const float*)d_in[1];
    const float* pC   = (const float*)d_in[2];
    const float* cell = (const float*)d_in[3];
    const float* Wx = (const float*)d_in[4];   const float* bx = (const float*)d_in[5];
    const float* Wh = (const float*)d_in[6];   const float* bh = (const float*)d_in[7];
    const float* WLC = (const float*)d_in[8];  const float* bLC = (const float*)d_in[9];
    const float* WC = (const float*)d_in[10];  const float* bC = (const float*)d_in[11];
    const float* WP = (const float*)d_in[12];  const float* bP = (const float*)d_in[13];
    const float* Wf = (const float*)d_in[14];  const float* bf = (const float*)d_in[15];
    const float* Wi = (const float*)d_in[16];  const float* bi = (const float*)d_in[17];
    const float* Wo = (const float*)d_in[18];  const float* bo = (const float*)d_in[19];
    const float* g1 = (const float*)d_in[20];  const float* be1 = (const float*)d_in[21];
    const float* g2 = (const float*)d_in[22];  const float* be2 = (const float*)d_in[23];
    const float* g3 = (const float*)d_in[24];  const float* be3 = (const float*)d_in[25];

    float* o = (float*)d_out;
    const size_t SEC = (size_t)BD * HD;
    float* sLC = o;            // LC_t   (LC_raw until k2)
    float* sNE = o + SEC;      // NE_t
    float* sCT = o + 2 * SEC;  // C_t    (base until k3 consumes it)
    float* sPU = o + 3 * SEC;  // Pupil  (igate until k3/k4)
    float* sNC = o + 4 * SEC;  // new_cell (NE_raw until k3)

    // idempotent; called every time (no static guards per harness contract)
    cudaFuncSetAttribute(k1a, cudaFuncAttributeMaxDynamicSharedMemorySize, SMEM_REQ);
    cudaFuncSetAttribute(k1b, cudaFuncAttributeMaxDynamicSharedMemorySize, SMEM_REQ);
    cudaFuncSetAttribute(k1c, cudaFuncAttributeMaxDynamicSharedMemorySize, SMEM_REQ);
    cudaFuncSetAttribute(k2, cudaFuncAttributeMaxDynamicSharedMemorySize, SMEM_REQ);
    cudaFuncSetAttribute(k3, cudaFuncAttributeMaxDynamicSharedMemorySize, SMEM_REQ);
    cudaFuncSetAttribute(k4, cudaFuncAttributeMaxDynamicSharedMemorySize, SMEM_REQ);

    dim3 blk(NTH);
    dim3 grd(BD / MT);

    k0_prep<<<HD + 1, NTH>>>(Wx, bx, Wi, bi, WC, bC);
    kW<<<dim3(HD, 7), NTH>>>(Wx, Wh, Wf, WLC, Wo);
    k1a<<<grd, blk, SMEM_REQ>>>(X, pLC, bx, bh, sLC);
    k1b<<<grd, blk, SMEM_REQ>>>(pC, X, bf, cell, sCT);
    k1c<<<grd, blk, SMEM_REQ>>>(X, sPU);
    k2<<<grd, blk, SMEM_REQ>>>(sLC, bLC, g1, be1, sNC);
    k3<<<grd, blk, SMEM_REQ>>>(sNC, sNE, bLC, sCT, sPU, g2, be2);
    k4<<<grd, blk, SMEM_REQ>>>(sNC, sCT, sLC, sNE, bo, WP, bP, g3, be3, sPU);
}

// round 11
// speedup vs baseline: 2.2806x; 1.2594x over previous
#include <cuda_runtime.h>
#include <cuda_bf16.h>
#include <math.h>
#include <stdint.h>

// LCNECortexLSTM B=65536, D=H=256 — mma.sync (HMMA bf16) split-precision pipeline.
// R11: CTA tile 128x128 (grid = BD/128 x 2 N-halves), warp tile 64x32,
// __launch_bounds__(256,2) -> 2 CTAs/SM. In-place transform races from R10 fixed
// via static device scratch: LC_raw in g_scr1, NE_raw in g_scr2 (transforms read
// scratch, write outputs; duplicate writes across N-half CTAs are identical).

#define BD 65536
#define HD 256
#define MT 128
#define NT 128
#define NTH 256

#define OFF_ALO 16384
#define OFF_BHI 32768
#define OFF_BLO 49152
#define OFF_SCALE 65536
#define OFF_SHIFT 66560
#define OFF_WP 67584
#define OFF_PS 68608
#define SMEM_REQ 70144

// weight images: [mat][hi/lo], transposed [N][K], chunked 4x(256 rows x 64 k),
// 128B rows with XOR-16B swizzle. mats: 0=Wx 1=Wh 2=Wf 3=WxWC 4=WxWi 5=WLC 6=Wo
__device__ __nv_bfloat16 g_Wimg[7][2][HD * HD];
__device__ float g_WxWi[HD * HD];
__device__ float g_WxWC[HD * HD];
__device__ float g_bxWi[HD];
__device__ float g_bxWC[HD];
__device__ float g_stats[6 * HD];
__device__ float g_scr1[(size_t)BD * HD];  // LC_raw
__device__ float g_scr2[(size_t)BD * HD];  // NE_raw

__device__ __forceinline__ float sigm(float x) { return 1.0f / (1.0f + expf(-x)); }
__device__ __forceinline__ float lky(float x) { return x > 0.0f ? x : 0.1f * x; }

__device__ __forceinline__ uint32_t smem_to_u32(const void* p) {
    uint32_t a;
    asm("{ .reg .u64 t; cvta.to.shared.u64 t, %1; cvt.u32.u64 %0, t; }" : "=r"(a) : "l"(p));
    return a;
}

__device__ __forceinline__ void ldsm_x4(uint32_t* r, uint32_t addr) {
    asm volatile("ldmatrix.sync.aligned.m8n8.x4.shared.b16 {%0,%1,%2,%3}, [%4];"
        : "=r"(r[0]), "=r"(r[1]), "=r"(r[2]), "=r"(r[3]) : "r"(addr));
}
__device__ __forceinline__ void ldsm_x2(uint32_t* r, uint32_t addr) {
    asm volatile("ldmatrix.sync.aligned.m8n8.x2.shared.b16 {%0,%1}, [%2];"
        : "=r"(r[0]), "=r"(r[1]) : "r"(addr));
}
__device__ __forceinline__ void mma_bf16(float* c, const uint32_t* a, const uint32_t* b) {
    asm volatile("mma.sync.aligned.m16n8k16.row.col.f32.bf16.bf16.f32 "
        "{%0,%1,%2,%3}, {%4,%5,%6,%7}, {%8,%9}, {%0,%1,%2,%3};"
        : "+f"(c[0]), "+f"(c[1]), "+f"(c[2]), "+f"(c[3])
        : "r"(a[0]), "r"(a[1]), "r"(a[2]), "r"(a[3]), "r"(b[0]), "r"(b[1]));
}

__device__ __forceinline__ uint32_t pack_split(float a, float b, uint32_t& lo) {
    __nv_bfloat162 h = __floats2bfloat162_rn(a, b);
    __nv_bfloat162 l = __floats2bfloat162_rn(a - __low2float(h), b - __high2float(h));
    lo = *reinterpret_cast<uint32_t*>(&l);
    return *reinterpret_cast<uint32_t*>(&h);
}

// linear copy of one pre-swizzled 16KB hi + 16KB lo half-chunk (this CTA's 128 N rows)
__device__ __forceinline__ void load_B(char* dh_, char* dl_,
                                       const __nv_bfloat16* Whi, const __nv_bfloat16* Wlo,
                                       int chunk, int ncol0, int tid) {
    const uint4* sh = (const uint4*)(Whi + chunk * 16384 + ncol0 * 64);
    const uint4* sl = (const uint4*)(Wlo + chunk * 16384 + ncol0 * 64);
    uint4* dh = (uint4*)dh_;
    uint4* dl = (uint4*)dl_;
#pragma unroll
    for (int i = 0; i < 4; i++) {
        dh[i * NTH + tid] = sh[i * NTH + tid];
        dl[i * NTH + tid] = sl[i * NTH + tid];
    }
}

// ---------------- kernel body macros ----------------

#define GEMM_PROLOG                                                           \
    extern __shared__ char dsm_[];                                            \
    char* smem = (char*)(((uintptr_t)dsm_ + 1023) & ~(uintptr_t)1023);        \
    const int tid = threadIdx.x, wid = tid >> 5, lane = tid & 31;             \
    const int wm = wid & 1, wn = wid >> 1;                                    \
    const int row0 = blockIdx.x * MT;                                         \
    const int ncol0 = blockIdx.y * NT;                                        \
    const uint32_t su = smem_to_u32(smem);                                    \
    char* sAhi = smem; char* sAlo = smem + OFF_ALO;                           \
    char* sBhi = smem + OFF_BHI; char* sBlo = smem + OFF_BLO;                 \
    const uint32_t uAhi = su, uAlo = su + OFF_ALO;                            \
    const uint32_t uBhi = su + OFF_BHI, uBlo = su + OFF_BLO;                  \
    float* sScale = (float*)(smem + OFF_SCALE);                               \
    float* sShift = (float*)(smem + OFF_SHIFT);                               \
    (void)sScale; (void)sShift; (void)sAlo; (void)sBlo;                       \
    float acc[4][4][4];                                                       \
    _Pragma("unroll") for (int i_ = 0; i_ < 4; i_++)                          \
        _Pragma("unroll") for (int j_ = 0; j_ < 4; j_++)                      \
            _Pragma("unroll") for (int q_ = 0; q_ < 4; q_++)                  \
                acc[i_][j_][q_] = 0.0f;

#define COMPUTE_CHUNK                                                         \
    __syncthreads();                                                          \
    _Pragma("unroll") for (int ks = 0; ks < 4; ks++) {                        \
        uint32_t ah[4][4], al[4][4];                                          \
        _Pragma("unroll") for (int mi = 0; mi < 4; mi++) {                    \
            int r = wm * 64 + mi * 16 + (lane & 15);                          \
            int kb = ks * 32 + ((lane & 16) ? 16 : 0);                        \
            uint32_t sw = (uint32_t)r * 128 + (kb ^ ((r & 7) << 4));          \
            ldsm_x4(ah[mi], uAhi + sw);                                       \
            ldsm_x4(al[mi], uAlo + sw);                                       \
        }                                                                     \
        _Pragma("unroll") for (int ni = 0; ni < 4; ni++) {                    \
            int l = lane & 15;                                                \
            int rn = wn * 32 + ni * 8 + (l & 7);                              \
            int kb = ks * 32 + ((l & 8) ? 16 : 0);                            \
            uint32_t sw = (uint32_t)rn * 128 + (kb ^ ((rn & 7) << 4));        \
            uint32_t bh2[2], bl2[2];                                          \
            ldsm_x2(bh2, uBhi + sw);                                          \
            ldsm_x2(bl2, uBlo + sw);                                          \
            _Pragma("unroll") for (int mi = 0; mi < 4; mi++) {                \
                mma_bf16(acc[mi][ni], ah[mi], bh2);                           \
                mma_bf16(acc[mi][ni], ah[mi], bl2);                           \
                mma_bf16(acc[mi][ni], al[mi], bh2);                           \
            }                                                                 \
        }                                                                     \
    }

#define SPLIT_STORE(av, r, cc)                                                \
    {                                                                         \
        uint2 h2, l2;                                                         \
        h2.x = pack_split((av).x, (av).y, l2.x);                              \
        h2.y = pack_split((av).z, (av).w, l2.y);                              \
        uint32_t off = (uint32_t)(r) * 128 + (((cc) * 2) ^ (((r) & 7) << 4)); \
        *(uint2*)(sAhi + off) = h2;                                           \
        *(uint2*)(sAlo + off) = l2;                                           \
    }

#define A_LOAD_PLAIN(SRC, KB)                                                 \
    {                                                                         \
        const int cr = tid >> 4, cc = (tid & 15) * 4;                         \
        _Pragma("unroll") for (int ii = 0; ii < 8; ii++) {                    \
            const int r = cr + ii * 16;                                       \
            float4 av = *(const float4*)((SRC) + (size_t)(row0 + r) * HD + (KB) + cc); \
            SPLIT_STORE(av, r, cc);                                           \
        }                                                                     \
    }

// SRC must be distinct from OUT (no in-place: both N-half CTAs read SRC and
// write identical transformed values to OUT)
#define A_LOAD_TRANS(SRC, OUT, KB)                                            \
    {                                                                         \
        const int cr = tid >> 4, cc = (tid & 15) * 4;                         \
        float4 sc = *(float4*)&sScale[(KB) + cc];                             \
        float4 sh = *(float4*)&sShift[(KB) + cc];                             \
        _Pragma("unroll") for (int ii = 0; ii < 8; ii++) {                    \
            const int r = cr + ii * 16;                                       \
            size_t gx = (size_t)(row0 + r) * HD + (KB) + cc;                  \
            float4 av = *(const float4*)((SRC) + gx);                         \
            av.x = lky(fmaf(av.x, sc.x, sh.x));                               \
            av.y = lky(fmaf(av.y, sc.y, sh.y));                               \
            av.z = lky(fmaf(av.z, sc.z, sh.z));                               \
            av.w = lky(fmaf(av.w, sc.w, sh.w));                               \
            *(float4*)((OUT) + gx) = av;                                      \
            SPLIT_STORE(av, r, cc);                                           \
        }                                                                     \
    }

#define A_LOAD_TP(SRC, OUT, LCP, NEP, KB)                                     \
    {                                                                         \
        const int cr = tid >> 4, cc = (tid & 15) * 4;                         \
        float4 sc = *(float4*)&sScale[(KB) + cc];                             \
        float4 sh = *(float4*)&sShift[(KB) + cc];                             \
        float4 wp = *(float4*)&sWP[(KB) + cc];                                \
        _Pragma("unroll") for (int ii = 0; ii < 8; ii++) {                    \
            const int r = cr + ii * 16;                                       \
            size_t gx = (size_t)(row0 + r) * HD + (KB) + cc;                  \
            float4 av = *(const float4*)((SRC) + gx);                         \
            av.x = lky(fmaf(av.x, sc.x, sh.x));                               \
            av.y = lky(fmaf(av.y, sc.y, sh.y));                               \
            av.z = lky(fmaf(av.z, sc.z, sh.z));                               \
            av.w = lky(fmaf(av.w, sc.w, sh.w));                               \
            *(float4*)((OUT) + gx) = av;                                      \
            float4 lv = *(const float4*)((LCP) + gx);                         \
            float4 nv = *(const float4*)((NEP) + gx);                         \
            pv[ii] = fmaf(av.x + lv.x + nv.x, wp.x, pv[ii]);                  \
            pv[ii] = fmaf(av.y + lv.y + nv.y, wp.y, pv[ii]);                  \
            pv[ii] = fmaf(av.z + lv.z + nv.z, wp.z, pv[ii]);                  \
            pv[ii] = fmaf(av.w + lv.w + nv.w, wp.w, pv[ii]);                  \
            SPLIT_STORE(av, r, cc);                                           \
        }                                                                     \
    }

// epilogue iteration: rr = global row, cb = global column (pair base)
#define EPI_BEGIN                                                             \
    _Pragma("unroll") for (int mi = 0; mi < 4; mi++) {                        \
        _Pragma("unroll") for (int h = 0; h < 2; h++) {                       \
            const int rr = row0 + wm * 64 + mi * 16 + (lane >> 2) + h * 8;    \
            _Pragma("unroll") for (int ni = 0; ni < 4; ni++) {                \
                const int cb = ncol0 + wn * 32 + ni * 8 + (lane & 3) * 2;     \
                float vx = acc[mi][ni][h * 2], vy = acc[mi][ni][h * 2 + 1];   \
                (void)cb;

#define EPI_END_STORE(OUT)                                                    \
                *(float2*)((OUT) + (size_t)rr * HD + cb) = make_float2(vx, vy); \
            } } }

#define EPI_END_ACC                                                           \
                acc[mi][ni][h * 2] = vx; acc[mi][ni][h * 2 + 1] = vy;         \
            } } }

#define STATS_DECL                                                            \
    float ssum[4][2], ssq[4][2];                                              \
    _Pragma("unroll") for (int i_ = 0; i_ < 4; i_++) {                        \
        ssum[i_][0] = ssum[i_][1] = 0.0f; ssq[i_][0] = ssq[i_][1] = 0.0f; }

#define STATS_ACC                                                             \
    ssum[ni][0] += vx; ssq[ni][0] += vx * vx;                                 \
    ssum[ni][1] += vy; ssq[ni][1] += vy * vy;

#define STATS_REDUCE(SIDX)                                                    \
    _Pragma("unroll") for (int ni = 0; ni < 4; ni++) {                        \
        _Pragma("unroll") for (int c2 = 0; c2 < 2; c2++) {                    \
            float s_ = ssum[ni][c2], q_ = ssq[ni][c2];                        \
            s_ += __shfl_xor_sync(~0u, s_, 4);  q_ += __shfl_xor_sync(~0u, q_, 4);  \
            s_ += __shfl_xor_sync(~0u, s_, 8);  q_ += __shfl_xor_sync(~0u, q_, 8);  \
            s_ += __shfl_xor_sync(~0u, s_, 16); q_ += __shfl_xor_sync(~0u, q_, 16); \
            if (lane < 4) {                                                   \
                int col = ncol0 + wn * 32 + ni * 8 + lane * 2 + c2;           \
                atomicAdd(&g_stats[(SIDX) * HD + col], s_);                   \
                atomicAdd(&g_stats[((SIDX) + 1) * HD + col], q_);             \
            } } }

#define BN_PREP(SIDX, G, B)                                                   \
    {                                                                         \
        float m_ = g_stats[(SIDX) * HD + tid] * (1.0f / (float)BD);           \
        float e2_ = g_stats[((SIDX) + 1) * HD + tid] * (1.0f / (float)BD);    \
        float rs_ = rsqrtf(e2_ - m_ * m_ + 1e-5f);                            \
        float sc_ = rs_ * (G)[tid];                                           \
        sScale[tid] = sc_;                                                    \
        sShift[tid] = (B)[tid] - m_ * sc_;                                    \
    }

// per-ni column-pair bias preload (4 tiles of 8 cols per warp)
#define BIAS4(DST, SRCP)                                                      \
    float2 DST[4];                                                            \
    _Pragma("unroll") for (int i_ = 0; i_ < 4; i_++)                          \
        DST[i_] = *(const float2*)((SRCP) + ncol0 + wn * 32 + i_ * 8 + (lane & 3) * 2);

// ---------------- prep kernels ----------------

__global__ void __launch_bounds__(NTH) k0_prep(
    const float* __restrict__ Wx, const float* __restrict__ bx,
    const float* __restrict__ Wi, const float* __restrict__ bi,
    const float* __restrict__ WC, const float* __restrict__ bC) {
    int h = threadIdx.x;
    if (blockIdx.x < HD) {
        __shared__ float sA[HD];
        sA[h] = Wx[blockIdx.x * HD + h];
        __syncthreads();
        float aI = 0.0f, aC = 0.0f;
#pragma unroll 4
        for (int k = 0; k < HD; k++) {
            float a = sA[k];
            aI = fmaf(a, Wi[k * HD + h], aI);
            aC = fmaf(a, WC[k * HD + h], aC);
        }
        g_WxWi[blockIdx.x * HD + h] = aI;
        g_WxWC[blockIdx.x * HD + h] = aC;
    } else {
        float aI = bi[h], aC = bC[h];
        for (int k = 0; k < HD; k++) {
            float a = bx[k];
            aI = fmaf(a, Wi[k * HD + h], aI);
            aC = fmaf(a, WC[k * HD + h], aC);
        }
        g_bxWi[h] = aI;
        g_bxWC[h] = aC;
#pragma unroll
        for (int s = 0; s < 6; s++) g_stats[s * HD + h] = 0.0f;
    }
}

// weights -> transposed [N][K] bf16 hi/lo, chunked by K=64, XOR-swizzled 128B rows
__global__ void __launch_bounds__(NTH) kW(
    const float* __restrict__ Wx, const float* __restrict__ Wh,
    const float* __restrict__ Wf, const float* __restrict__ WLC,
    const float* __restrict__ Wo) {
    int k = blockIdx.x, m = blockIdx.y, n = threadIdx.x;
    const float* src;
    switch (m) {
        case 0: src = Wx; break;
        case 1: src = Wh; break;
        case 2: src = Wf; break;
        case 3: src = g_WxWC; break;
        case 4: src = g_WxWi; break;
        case 5: src = WLC; break;
        default: src = Wo; break;
    }
    float val = src[k * HD + n];
    __nv_bfloat16 h = __float2bfloat16(val);
    __nv_bfloat16 l = __float2bfloat16(val - __bfloat162float(h));
    int chunk = k >> 6, kk = k & 63;
    uint32_t off = (uint32_t)chunk * 32768 + (uint32_t)n * 128 + ((kk * 2) ^ ((n & 7) << 4));
    *(__nv_bfloat16*)((char*)g_Wimg[m][0] + off) = h;
    *(__nv_bfloat16*)((char*)g_Wimg[m][1] + off) = l;
}

// ---------------- GEMM kernels ----------------

// k1a: LC_raw = X@Wx + pLC@Wh + (bx+bh) -> g_scr1; stats0
__global__ void __launch_bounds__(NTH, 2) k1a(
    const float* __restrict__ X, const float* __restrict__ pLC,
    const float* __restrict__ bx, const float* __restrict__ bh_) {
    GEMM_PROLOG;
#pragma unroll 1
    for (int c = 0; c < 8; c++) {
        __syncthreads();
        const float* src = (c < 4) ? X : pLC;
        int mat = (c < 4) ? 0 : 1;
        int cc4 = c & 3;
        A_LOAD_PLAIN(src, cc4 * 64);
        load_B(sBhi, sBlo, g_Wimg[mat][0], g_Wimg[mat][1], cc4, ncol0, tid);
        COMPUTE_CHUNK;
    }
    BIAS4(b1, bx); BIAS4(b2, bh_);
    STATS_DECL;
    EPI_BEGIN;
    vx += b1[ni].x + b2[ni].x;
    vy += b1[ni].y + b2[ni].y;
    STATS_ACC;
    EPI_END_STORE(g_scr1);
    STATS_REDUCE(0);
}

// k1b: base = sigmoid(pC@Wf+bf)*cell + X@WxWC + bxWC -> sec2 (mid-transform)
__global__ void __launch_bounds__(NTH, 2) k1b(
    const float* __restrict__ pC, const float* __restrict__ X,
    const float* __restrict__ bf_, const float* __restrict__ cell, float* out) {
    GEMM_PROLOG;
#pragma unroll 1
    for (int c = 0; c < 4; c++) {
        __syncthreads();
        A_LOAD_PLAIN(pC, c * 64);
        load_B(sBhi, sBlo, g_Wimg[2][0], g_Wimg[2][1], c, ncol0, tid);
        COMPUTE_CHUNK;
    }
    {
        BIAS4(bfv, bf_);
        EPI_BEGIN;
        float2 cv = *(const float2*)(cell + (size_t)rr * HD + cb);
        vx = sigm(vx + bfv[ni].x) * cv.x;
        vy = sigm(vy + bfv[ni].y) * cv.y;
        EPI_END_ACC;
    }
#pragma unroll 1
    for (int c = 0; c < 4; c++) {
        __syncthreads();
        A_LOAD_PLAIN(X, c * 64);
        load_B(sBhi, sBlo, g_Wimg[3][0], g_Wimg[3][1], c, ncol0, tid);
        COMPUTE_CHUNK;
    }
    BIAS4(bb, g_bxWC);
    EPI_BEGIN;
    vx += bb[ni].x;
    vy += bb[ni].y;
    EPI_END_STORE(out);
}

// k1c: igate = sigmoid(X@WxWi + bxWi) -> sec3
__global__ void __launch_bounds__(NTH, 2) k1c(const float* __restrict__ X, float* out) {
    GEMM_PROLOG;
#pragma unroll 1
    for (int c = 0; c < 4; c++) {
        __syncthreads();
        A_LOAD_PLAIN(X, c * 64);
        load_B(sBhi, sBlo, g_Wimg[4][0], g_Wimg[4][1], c, ncol0, tid);
        COMPUTE_CHUNK;
    }
    BIAS4(bb, g_bxWi);
    EPI_BEGIN;
    vx = sigm(vx + bb[ni].x);
    vy = sigm(vy + bb[ni].y);
    EPI_END_STORE(out);
}

// k2: LC_t = leaky(bn1(g_scr1)) -> sec0; NE_raw = LC_t@WLC + bLC -> g_scr2; stats2
__global__ void __launch_bounds__(NTH, 2) k2(
    float* out_lct, const float* __restrict__ bLC,
    const float* __restrict__ g1, const float* __restrict__ be1) {
    GEMM_PROLOG;
    BN_PREP(0, g1, be1);
#pragma unroll 1
    for (int c = 0; c < 4; c++) {
        __syncthreads();
        A_LOAD_TRANS(g_scr1, out_lct, c * 64);
        load_B(sBhi, sBlo, g_Wimg[5][0], g_Wimg[5][1], c, ncol0, tid);
        COMPUTE_CHUNK;
    }
    BIAS4(bb, bLC);
    STATS_DECL;
    EPI_BEGIN;
    vx += bb[ni].x;
    vy += bb[ni].y;
    STATS_ACC;
    EPI_END_STORE(g_scr2);
    STATS_REDUCE(2);
}

// k3: NE_t = leaky(bn2(g_scr2)) -> sec1; new_cell = base + ig*0.1*(NE_t@WLC+bLC) -> sec4; stats4
__global__ void __launch_bounds__(NTH, 2) k3(
    float* out_nc, float* out_net, const float* __restrict__ bLC,
    const float* __restrict__ base, const float* __restrict__ ig,
    const float* __restrict__ g2, const float* __restrict__ be2) {
    GEMM_PROLOG;
    BN_PREP(2, g2, be2);
#pragma unroll 1
    for (int c = 0; c < 4; c++) {
        __syncthreads();
        A_LOAD_TRANS(g_scr2, out_net, c * 64);
        load_B(sBhi, sBlo, g_Wimg[5][0], g_Wimg[5][1], c, ncol0, tid);
        COMPUTE_CHUNK;
    }
    BIAS4(bb, bLC);
    STATS_DECL;
    EPI_BEGIN;
    float2 bv = *(const float2*)(base + (size_t)rr * HD + cb);
    float2 iv = *(const float2*)(ig + (size_t)rr * HD + cb);
    vx = fmaf(iv.x * 0.1f, vx + bb[ni].x, bv.x);
    vy = fmaf(iv.y * 0.1f, vy + bb[ni].y, bv.y);
    STATS_ACC;
    EPI_END_STORE(out_nc);
    STATS_REDUCE(4);
}

// k4: C_t = leaky(bn3(sec4)) -> sec2; p = (LC_t+C_t+NE_t)@WP;
//     Pupil = sigmoid(C_t@Wo+bo)*(p+bP) -> sec3
__global__ void __launch_bounds__(NTH, 2) k4(
    const float* __restrict__ ncell, float* out_ct,
    const float* __restrict__ lct, const float* __restrict__ net,
    const float* __restrict__ bo, const float* __restrict__ WP,
    const float* __restrict__ bP, const float* __restrict__ g3,
    const float* __restrict__ be3, float* out_pupil) {
    GEMM_PROLOG;
    BN_PREP(4, g3, be3);
    float* sWP = (float*)(smem + OFF_WP);
    float* p_s = (float*)(smem + OFF_PS);
    sWP[tid] = WP[tid];
    if (tid < MT) p_s[tid] = 0.0f;
    float pv[8];
#pragma unroll
    for (int i = 0; i < 8; i++) pv[i] = 0.0f;
#pragma unroll 1
    for (int c = 0; c < 4; c++) {
        __syncthreads();
        A_LOAD_TP(ncell, out_ct, lct, net, c * 64);
        load_B(sBhi, sBlo, g_Wimg[6][0], g_Wimg[6][1], c, ncol0, tid);
        COMPUTE_CHUNK;
    }
    {
        const int crr = tid >> 4;
#pragma unroll
        for (int ii = 0; ii < 8; ii++) atomicAdd(&p_s[crr + ii * 16], pv[ii]);
    }
    __syncthreads();
    float bP0 = bP[0];
    BIAS4(bb, bo);
    EPI_BEGIN;
    float pr = p_s[rr - row0] + bP0;
    vx = sigm(vx + bb[ni].x) * pr;
    vy = sigm(vy + bb[ni].y) * pr;
    EPI_END_STORE(out_pupil);
}

// ---------------- launch ----------------

extern "C" void kernel_launch(void* const* d_in, const int* in_sizes, int n_in,
                              void* d_out, int out_size) {
    (void)in_sizes; (void)n_in; (void)out_size;
    const float* X    = (const float*)d_in[0];
    const float* pLC  = (const float*)d_in[1];
    const float* pC   = (const float*)d_in[2];
    const float* cell = (const float*)d_in[3];
    const float* Wx = (const float*)d_in[4];   const float* bx = (const float*)d_in[5];
    const float* Wh = (const float*)d_in[6];   const float* bh = (const float*)d_in[7];
    const float* WLC = (const float*)d_in[8];  const float* bLC = (const float*)d_in[9];
    const float* WC = (const float*)d_in[10];  const float* bC = (const float*)d_in[11];
    const float* WP = (const float*)d_in[12];  const float* bP = (const float*)d_in[13];
    const float* Wf = (const float*)d_in[14];  const float* bf = (const float*)d_in[15];
    const float* Wi = (const float*)d_in[16];  const float* bi = (const float*)d_in[17];
    const float* Wo = (const float*)d_in[18];  const float* bo = (const float*)d_in[19];
    const float* g1 = (const float*)d_in[20];  const float* be1 = (const float*)d_in[21];
    const float* g2 = (const float*)d_in[22];  const float* be2 = (const float*)d_in[23];
    const float* g3 = (const float*)d_in[24];  const float* be3 = (const float*)d_in[25];

    float* o = (float*)d_out;
    const size_t SEC = (size_t)BD * HD;
    float* sLC = o;            // LC_t   (written by k2)
    float* sNE = o + SEC;      // NE_t   (written by k3)
    float* sCT = o + 2 * SEC;  // C_t    (base until k3 consumes it; k4 writes C_t)
    float* sPU = o + 3 * SEC;  // Pupil  (igate until k3; k4 writes Pupil)
    float* sNC = o + 4 * SEC;  // new_cell (written by k3)

    // idempotent; called every time (no static guards per harness contract)
    cudaFuncSetAttribute(k1a, cudaFuncAttributeMaxDynamicSharedMemorySize, SMEM_REQ);
    cudaFuncSetAttribute(k1b, cudaFuncAttributeMaxDynamicSharedMemorySize, SMEM_REQ);
    cudaFuncSetAttribute(k1c, cudaFuncAttributeMaxDynamicSharedMemorySize, SMEM_REQ);
    cudaFuncSetAttribute(k2, cudaFuncAttributeMaxDynamicSharedMemorySize, SMEM_REQ);
    cudaFuncSetAttribute(k3, cudaFuncAttributeMaxDynamicSharedMemorySize, SMEM_REQ);
    cudaFuncSetAttribute(k4, cudaFuncAttributeMaxDynamicSharedMemorySize, SMEM_REQ);

    dim3 blk(NTH);
    dim3 grd(BD / MT, HD / NT);

    k0_prep<<<HD + 1, NTH>>>(Wx, bx, Wi, bi, WC, bC);
    kW<<<dim3(HD, 7), NTH>>>(Wx, Wh, Wf, WLC, Wo);
    k1a<<<grd, blk, SMEM_REQ>>>(X, pLC, bx, bh);
    k1b<<<grd, blk, SMEM_REQ>>>(pC, X, bf, cell, sCT);
    k1c<<<grd, blk, SMEM_REQ>>>(X, sPU);
    k2<<<grd, blk, SMEM_REQ>>>(sLC, bLC, g1, be1);
    k3<<<grd, blk, SMEM_REQ>>>(sNC, sNE, bLC, sCT, sPU, g2, be2);
    k4<<<grd, blk, SMEM_REQ>>>(sNC, sCT, sLC, sNE, bo, WP, bP, g3, be3, sPU);
}

// round 12
// speedup vs baseline: 3.4173x; 1.4984x over previous
#include <cuda_runtime.h>
#include <cuda_bf16.h>
#include <math.h>
#include <stdint.h>

// LCNECortexLSTM B=65536, D=H=256 — mma.sync (HMMA bf16) split-precision pipeline.
// R12: cp.async software pipeline. Raw fp32 A chunk staged in SMEM (32KB) with
// cp.async overlapping the previous chunk's MMA burst; transform reads SMEM.
// B (L2-warm weights) cp.async'd during the transform phase.
// CTA tile 128x128, warp tile 64x32, __launch_bounds__(256,2) -> 2 CTAs/SM.
// D_fp32 = Ahi@Bhi + Ahi@Blo + Alo@Bhi.

#define BD 65536
#define HD 256
#define MT 128
#define NT 128
#define NTH 256

#define OFF_RAW 0
#define OFF_AHI 32768
#define OFF_ALO 49152
#define OFF_BHI 65536
#define OFF_BLO 81920
#define OFF_SCALE 98304
#define OFF_SHIFT 99328
#define OFF_WP 100352
#define OFF_PS 101376
#define SMEM_REQ 102912

// weight images: [mat][hi/lo], transposed [N][K], chunked 4x(256 rows x 64 k),
// 128B rows with XOR-16B swizzle. mats: 0=Wx 1=Wh 2=Wf 3=WxWC 4=WxWi 5=WLC 6=Wo
__device__ __nv_bfloat16 g_Wimg[7][2][HD * HD];
__device__ float g_WxWi[HD * HD];
__device__ float g_WxWC[HD * HD];
__device__ float g_bxWi[HD];
__device__ float g_bxWC[HD];
__device__ float g_stats[6 * HD];
__device__ float g_scr1[(size_t)BD * HD];  // LC_raw
__device__ float g_scr2[(size_t)BD * HD];  // NE_raw

__device__ __forceinline__ float sigm(float x) { return 1.0f / (1.0f + expf(-x)); }
__device__ __forceinline__ float lky(float x) { return x > 0.0f ? x : 0.1f * x; }

__device__ __forceinline__ uint32_t smem_to_u32(const void* p) {
    uint32_t a;
    asm("{ .reg .u64 t; cvta.to.shared.u64 t, %1; cvt.u32.u64 %0, t; }" : "=r"(a) : "l"(p));
    return a;
}

__device__ __forceinline__ void ldsm_x4(uint32_t* r, uint32_t addr) {
    asm volatile("ldmatrix.sync.aligned.m8n8.x4.shared.b16 {%0,%1,%2,%3}, [%4];"
        : "=r"(r[0]), "=r"(r[1]), "=r"(r[2]), "=r"(r[3]) : "r"(addr));
}
__device__ __forceinline__ void ldsm_x2(uint32_t* r, uint32_t addr) {
    asm volatile("ldmatrix.sync.aligned.m8n8.x2.shared.b16 {%0,%1}, [%2];"
        : "=r"(r[0]), "=r"(r[1]) : "r"(addr));
}
__device__ __forceinline__ void mma_bf16(float* c, const uint32_t* a, const uint32_t* b) {
    asm volatile("mma.sync.aligned.m16n8k16.row.col.f32.bf16.bf16.f32 "
        "{%0,%1,%2,%3}, {%4,%5,%6,%7}, {%8,%9}, {%0,%1,%2,%3};"
        : "+f"(c[0]), "+f"(c[1]), "+f"(c[2]), "+f"(c[3])
        : "r"(a[0]), "r"(a[1]), "r"(a[2]), "r"(a[3]), "r"(b[0]), "r"(b[1]));
}
__device__ __forceinline__ void cp16(uint32_t dst, const void* src) {
    asm volatile("cp.async.cg.shared.global [%0], [%1], 16;" :: "r"(dst), "l"(src));
}

__device__ __forceinline__ uint32_t pack_split(float a, float b, uint32_t& lo) {
    __nv_bfloat162 h = __floats2bfloat162_rn(a, b);
    __nv_bfloat162 l = __floats2bfloat162_rn(a - __low2float(h), b - __high2float(h));
    lo = *reinterpret_cast<uint32_t*>(&l);
    return *reinterpret_cast<uint32_t*>(&h);
}

// ---------------- kernel body macros ----------------

#define GEMM_PROLOG                                                           \
    extern __shared__ char dsm_[];                                            \
    char* smem = (char*)(((uintptr_t)dsm_ + 1023) & ~(uintptr_t)1023);        \
    const int tid = threadIdx.x, wid = tid >> 5, lane = tid & 31;             \
    const int wm = wid & 1, wn = wid >> 1;                                    \
    const int row0 = blockIdx.x * MT;                                         \
    const int ncol0 = blockIdx.y * NT;                                        \
    const uint32_t su = smem_to_u32(smem);                                    \
    char* sRAW = smem + OFF_RAW;                                              \
    char* sAhi = smem + OFF_AHI; char* sAlo = smem + OFF_ALO;                 \
    const uint32_t uRAW = su + OFF_RAW;                                       \
    const uint32_t uAhi = su + OFF_AHI, uAlo = su + OFF_ALO;                  \
    const uint32_t uBhi = su + OFF_BHI, uBlo = su + OFF_BLO;                  \
    float* sScale = (float*)(smem + OFF_SCALE);                               \
    float* sShift = (float*)(smem + OFF_SHIFT);                               \
    (void)sScale; (void)sShift; (void)sRAW; (void)sAlo;                       \
    float acc[4][4][4];                                                       \
    _Pragma("unroll") for (int i_ = 0; i_ < 4; i_++)                          \
        _Pragma("unroll") for (int j_ = 0; j_ < 4; j_++)                      \
            _Pragma("unroll") for (int q_ = 0; q_ < 4; q_++)                  \
                acc[i_][j_][q_] = 0.0f;

// cp.async one raw fp32 A chunk (128 rows x 64 cols) into sRAW; commits a group.
#define A_CPASYNC(SRC, KB)                                                    \
    {                                                                         \
        const int pr_ = tid >> 4, ps_ = (tid & 15) * 16;                      \
        _Pragma("unroll") for (int ii = 0; ii < 8; ii++) {                    \
            int r_ = pr_ + ii * 16;                                           \
            cp16(uRAW + (uint32_t)r_ * 256 + ps_,                             \
                 (const char*)((SRC) + (size_t)(row0 + r_) * HD + (KB)) + ps_); \
        }                                                                     \
        asm volatile("cp.async.commit_group;" ::: "memory");                  \
    }

// cp.async one pre-swizzled B half-chunk (16KB hi + 16KB lo); commits a group.
#define B_CPASYNC(WHI, WLO, CH)                                               \
    {                                                                         \
        const char* bh_ = (const char*)((WHI) + (CH) * 16384 + ncol0 * 64);   \
        const char* bl_ = (const char*)((WLO) + (CH) * 16384 + ncol0 * 64);   \
        _Pragma("unroll") for (int i = 0; i < 4; i++) {                       \
            uint32_t o_ = (uint32_t)(i * NTH + tid) * 16;                     \
            cp16(uBhi + o_, bh_ + o_);                                        \
            cp16(uBlo + o_, bl_ + o_);                                        \
        }                                                                     \
        asm volatile("cp.async.commit_group;" ::: "memory");                  \
    }

#define PIPE_WAIT_SYNC                                                        \
    asm volatile("cp.async.wait_group 0;" ::: "memory");                      \
    __syncthreads();

#define COMPUTE_CHUNK                                                         \
    _Pragma("unroll") for (int ks = 0; ks < 4; ks++) {                        \
        uint32_t ah[4][4], al[4][4];                                          \
        _Pragma("unroll") for (int mi = 0; mi < 4; mi++) {                    \
            int r = wm * 64 + mi * 16 + (lane & 15);                          \
            int kb = ks * 32 + ((lane & 16) ? 16 : 0);                        \
            uint32_t sw = (uint32_t)r * 128 + (kb ^ ((r & 7) << 4));          \
            ldsm_x4(ah[mi], uAhi + sw);                                       \
            ldsm_x4(al[mi], uAlo + sw);                                       \
        }                                                                     \
        _Pragma("unroll") for (int ni = 0; ni < 4; ni++) {                    \
            int l = lane & 15;                                                \
            int rn = wn * 32 + ni * 8 + (l & 7);                              \
            int kb = ks * 32 + ((l & 8) ? 16 : 0);                            \
            uint32_t sw = (uint32_t)rn * 128 + (kb ^ ((rn & 7) << 4));        \
            uint32_t bh2[2], bl2[2];                                          \
            ldsm_x2(bh2, uBhi + sw);                                          \
            ldsm_x2(bl2, uBlo + sw);                                          \
            _Pragma("unroll") for (int mi = 0; mi < 4; mi++) {                \
                mma_bf16(acc[mi][ni], ah[mi], bh2);                           \
                mma_bf16(acc[mi][ni], ah[mi], bl2);                           \
                mma_bf16(acc[mi][ni], al[mi], bh2);                           \
            }                                                                 \
        }                                                                     \
    }

#define SPLIT_STORE(av, r, cc)                                                \
    {                                                                         \
        uint2 h2, l2;                                                         \
        h2.x = pack_split((av).x, (av).y, l2.x);                              \
        h2.y = pack_split((av).z, (av).w, l2.y);                              \
        uint32_t off = (uint32_t)(r) * 128 + (((cc) * 2) ^ (((r) & 7) << 4)); \
        *(uint2*)(sAhi + off) = h2;                                           \
        *(uint2*)(sAlo + off) = l2;                                           \
    }

// transforms read the raw chunk from SMEM (cp.async-staged)
#define A_TRANS_PLAIN                                                         \
    {                                                                         \
        const int cr = tid >> 4, cc = (tid & 15) * 4;                         \
        _Pragma("unroll") for (int ii = 0; ii < 8; ii++) {                    \
            const int r = cr + ii * 16;                                       \
            float4 av = *(const float4*)(sRAW + r * 256 + cc * 4);            \
            SPLIT_STORE(av, r, cc);                                           \
        }                                                                     \
    }

#define A_TRANS_BN(OUT, KB)                                                   \
    {                                                                         \
        const int cr = tid >> 4, cc = (tid & 15) * 4;                         \
        float4 sc = *(float4*)&sScale[(KB) + cc];                             \
        float4 sh = *(float4*)&sShift[(KB) + cc];                             \
        _Pragma("unroll") for (int ii = 0; ii < 8; ii++) {                    \
            const int r = cr + ii * 16;                                       \
            float4 av = *(const float4*)(sRAW + r * 256 + cc * 4);            \
            av.x = lky(fmaf(av.x, sc.x, sh.x));                               \
            av.y = lky(fmaf(av.y, sc.y, sh.y));                               \
            av.z = lky(fmaf(av.z, sc.z, sh.z));                               \
            av.w = lky(fmaf(av.w, sc.w, sh.w));                               \
            *(float4*)((OUT) + (size_t)(row0 + r) * HD + (KB) + cc) = av;     \
            SPLIT_STORE(av, r, cc);                                           \
        }                                                                     \
    }

#define A_TRANS_TP(OUT, LCP, NEP, KB)                                         \
    {                                                                         \
        const int cr = tid >> 4, cc = (tid & 15) * 4;                         \
        float4 sc = *(float4*)&sScale[(KB) + cc];                             \
        float4 sh = *(float4*)&sShift[(KB) + cc];                             \
        float4 wp = *(float4*)&sWP[(KB) + cc];                                \
        _Pragma("unroll") for (int ii = 0; ii < 8; ii++) {                    \
            const int r = cr + ii * 16;                                       \
            size_t gx = (size_t)(row0 + r) * HD + (KB) + cc;                  \
            float4 av = *(const float4*)(sRAW + r * 256 + cc * 4);            \
            av.x = lky(fmaf(av.x, sc.x, sh.x));                               \
            av.y = lky(fmaf(av.y, sc.y, sh.y));                               \
            av.z = lky(fmaf(av.z, sc.z, sh.z));                               \
            av.w = lky(fmaf(av.w, sc.w, sh.w));                               \
            *(float4*)((OUT) + gx) = av;                                      \
            float4 lv = *(const float4*)((LCP) + gx);                         \
            float4 nv = *(const float4*)((NEP) + gx);                         \
            pv[ii] = fmaf(av.x + lv.x + nv.x, wp.x, pv[ii]);                  \
            pv[ii] = fmaf(av.y + lv.y + nv.y, wp.y, pv[ii]);                  \
            pv[ii] = fmaf(av.z + lv.z + nv.z, wp.z, pv[ii]);                  \
            pv[ii] = fmaf(av.w + lv.w + nv.w, wp.w, pv[ii]);                  \
            SPLIT_STORE(av, r, cc);                                           \
        }                                                                     \
    }

// epilogue iteration: rr = global row, cb = global column (pair base)
#define EPI_BEGIN                                                             \
    _Pragma("unroll") for (int mi = 0; mi < 4; mi++) {                        \
        _Pragma("unroll") for (int h = 0; h < 2; h++) {                       \
            const int rr = row0 + wm * 64 + mi * 16 + (lane >> 2) + h * 8;    \
            _Pragma("unroll") for (int ni = 0; ni < 4; ni++) {                \
                const int cb = ncol0 + wn * 32 + ni * 8 + (lane & 3) * 2;     \
                float vx = acc[mi][ni][h * 2], vy = acc[mi][ni][h * 2 + 1];   \
                (void)cb;

#define EPI_END_STORE(OUT)                                                    \
                *(float2*)((OUT) + (size_t)rr * HD + cb) = make_float2(vx, vy); \
            } } }

#define EPI_END_ACC                                                           \
                acc[mi][ni][h * 2] = vx; acc[mi][ni][h * 2 + 1] = vy;         \
            } } }

#define STATS_DECL                                                            \
    float ssum[4][2], ssq[4][2];                                              \
    _Pragma("unroll") for (int i_ = 0; i_ < 4; i_++) {                        \
        ssum[i_][0] = ssum[i_][1] = 0.0f; ssq[i_][0] = ssq[i_][1] = 0.0f; }

#define STATS_ACC                                                             \
    ssum[ni][0] += vx; ssq[ni][0] += vx * vx;                                 \
    ssum[ni][1] += vy; ssq[ni][1] += vy * vy;

#define STATS_REDUCE(SIDX)                                                    \
    _Pragma("unroll") for (int ni = 0; ni < 4; ni++) {                        \
        _Pragma("unroll") for (int c2 = 0; c2 < 2; c2++) {                    \
            float s_ = ssum[ni][c2], q_ = ssq[ni][c2];                        \
            s_ += __shfl_xor_sync(~0u, s_, 4);  q_ += __shfl_xor_sync(~0u, q_, 4);  \
            s_ += __shfl_xor_sync(~0u, s_, 8);  q_ += __shfl_xor_sync(~0u, q_, 8);  \
            s_ += __shfl_xor_sync(~0u, s_, 16); q_ += __shfl_xor_sync(~0u, q_, 16); \
            if (lane < 4) {                                                   \
                int col = ncol0 + wn * 32 + ni * 8 + lane * 2 + c2;           \
                atomicAdd(&g_stats[(SIDX) * HD + col], s_);                   \
                atomicAdd(&g_stats[((SIDX) + 1) * HD + col], q_);             \
            } } }

#define BN_PREP(SIDX, G, B)                                                   \
    {                                                                         \
        float m_ = g_stats[(SIDX) * HD + tid] * (1.0f / (float)BD);           \
        float e2_ = g_stats[((SIDX) + 1) * HD + tid] * (1.0f / (float)BD);    \
        float rs_ = rsqrtf(e2_ - m_ * m_ + 1e-5f);                            \
        float sc_ = rs_ * (G)[tid];                                           \
        sScale[tid] = sc_;                                                    \
        sShift[tid] = (B)[tid] - m_ * sc_;                                    \
    }

#define BIAS4(DST, SRCP)                                                      \
    float2 DST[4];                                                            \
    _Pragma("unroll") for (int i_ = 0; i_ < 4; i_++)                          \
        DST[i_] = *(const float2*)((SRCP) + ncol0 + wn * 32 + i_ * 8 + (lane & 3) * 2);

// ---------------- prep kernels ----------------

__global__ void __launch_bounds__(NTH) k0_prep(
    const float* __restrict__ Wx, const float* __restrict__ bx,
    const float* __restrict__ Wi, const float* __restrict__ bi,
    const float* __restrict__ WC, const float* __restrict__ bC) {
    int h = threadIdx.x;
    if (blockIdx.x < HD) {
        __shared__ float sA[HD];
        sA[h] = Wx[blockIdx.x * HD + h];
        __syncthreads();
        float aI = 0.0f, aC = 0.0f;
#pragma unroll 4
        for (int k = 0; k < HD; k++) {
            float a = sA[k];
            aI = fmaf(a, Wi[k * HD + h], aI);
            aC = fmaf(a, WC[k * HD + h], aC);
        }
        g_WxWi[blockIdx.x * HD + h] = aI;
        g_WxWC[blockIdx.x * HD + h] = aC;
    } else {
        float aI = bi[h], aC = bC[h];
        for (int k = 0; k < HD; k++) {
            float a = bx[k];
            aI = fmaf(a, Wi[k * HD + h], aI);
            aC = fmaf(a, WC[k * HD + h], aC);
        }
        g_bxWi[h] = aI;
        g_bxWC[h] = aC;
#pragma unroll
        for (int s = 0; s < 6; s++) g_stats[s * HD + h] = 0.0f;
    }
}

// weights -> transposed [N][K] bf16 hi/lo, chunked by K=64, XOR-swizzled 128B rows
__global__ void __launch_bounds__(NTH) kW(
    const float* __restrict__ Wx, const float* __restrict__ Wh,
    const float* __restrict__ Wf, const float* __restrict__ WLC,
    const float* __restrict__ Wo) {
    int k = blockIdx.x, m = blockIdx.y, n = threadIdx.x;
    const float* src;
    switch (m) {
        case 0: src = Wx; break;
        case 1: src = Wh; break;
        case 2: src = Wf; break;
        case 3: src = g_WxWC; break;
        case 4: src = g_WxWi; break;
        case 5: src = WLC; break;
        default: src = Wo; break;
    }
    float val = src[k * HD + n];
    __nv_bfloat16 h = __float2bfloat16(val);
    __nv_bfloat16 l = __float2bfloat16(val - __bfloat162float(h));
    int chunk = k >> 6, kk = k & 63;
    uint32_t off = (uint32_t)chunk * 32768 + (uint32_t)n * 128 + ((kk * 2) ^ ((n & 7) << 4));
    *(__nv_bfloat16*)((char*)g_Wimg[m][0] + off) = h;
    *(__nv_bfloat16*)((char*)g_Wimg[m][1] + off) = l;
}

// ---------------- GEMM kernels ----------------

// k1a: LC_raw = X@Wx + pLC@Wh + (bx+bh) -> g_scr1; stats0
__global__ void __launch_bounds__(NTH, 2) k1a(
    const float* __restrict__ X, const float* __restrict__ pLC,
    const float* __restrict__ bx, const float* __restrict__ bh_) {
    GEMM_PROLOG;
    A_CPASYNC(X, 0);
#pragma unroll 1
    for (int c = 0; c < 8; c++) {
        PIPE_WAIT_SYNC;  // rawA_c ready
        int mat = (c < 4) ? 0 : 1;
        B_CPASYNC(g_Wimg[mat][0], g_Wimg[mat][1], c & 3);
        A_TRANS_PLAIN;
        PIPE_WAIT_SYNC;  // B ready; raw buffer free
        if (c < 7) {
            const float* nsrc = (c + 1 < 4) ? X : pLC;
            A_CPASYNC(nsrc, ((c + 1) & 3) * 64);
        }
        COMPUTE_CHUNK;
    }
    BIAS4(b1, bx); BIAS4(b2, bh_);
    STATS_DECL;
    EPI_BEGIN;
    vx += b1[ni].x + b2[ni].x;
    vy += b1[ni].y + b2[ni].y;
    STATS_ACC;
    EPI_END_STORE(g_scr1);
    STATS_REDUCE(0);
}

// k1b: base = sigmoid(pC@Wf+bf)*cell + X@WxWC + bxWC -> sec2 (mid-transform at c==3)
__global__ void __launch_bounds__(NTH, 2) k1b(
    const float* __restrict__ pC, const float* __restrict__ X,
    const float* __restrict__ bf_, const float* __restrict__ cell, float* out) {
    GEMM_PROLOG;
    A_CPASYNC(pC, 0);
#pragma unroll 1
    for (int c = 0; c < 8; c++) {
        PIPE_WAIT_SYNC;
        int mat = (c < 4) ? 2 : 3;
        B_CPASYNC(g_Wimg[mat][0], g_Wimg[mat][1], c & 3);
        A_TRANS_PLAIN;
        PIPE_WAIT_SYNC;
        if (c < 7) {
            const float* nsrc = (c + 1 < 4) ? pC : X;
            A_CPASYNC(nsrc, ((c + 1) & 3) * 64);
        }
        COMPUTE_CHUNK;
        if (c == 3) {
            BIAS4(bfv, bf_);
            EPI_BEGIN;
            float2 cv = *(const float2*)(cell + (size_t)rr * HD + cb);
            vx = sigm(vx + bfv[ni].x) * cv.x;
            vy = sigm(vy + bfv[ni].y) * cv.y;
            EPI_END_ACC;
        }
    }
    BIAS4(bb, g_bxWC);
    EPI_BEGIN;
    vx += bb[ni].x;
    vy += bb[ni].y;
    EPI_END_STORE(out);
}

// k1c: igate = sigmoid(X@WxWi + bxWi) -> sec3
__global__ void __launch_bounds__(NTH, 2) k1c(const float* __restrict__ X, float* out) {
    GEMM_PROLOG;
    A_CPASYNC(X, 0);
#pragma unroll 1
    for (int c = 0; c < 4; c++) {
        PIPE_WAIT_SYNC;
        B_CPASYNC(g_Wimg[4][0], g_Wimg[4][1], c);
        A_TRANS_PLAIN;
        PIPE_WAIT_SYNC;
        if (c < 3) A_CPASYNC(X, (c + 1) * 64);
        COMPUTE_CHUNK;
    }
    BIAS4(bb, g_bxWi);
    EPI_BEGIN;
    vx = sigm(vx + bb[ni].x);
    vy = sigm(vy + bb[ni].y);
    EPI_END_STORE(out);
}

// k2: LC_t = leaky(bn1(g_scr1)) -> sec0; NE_raw = LC_t@WLC + bLC -> g_scr2; stats2
__global__ void __launch_bounds__(NTH, 2) k2(
    float* out_lct, const float* __restrict__ bLC,
    const float* __restrict__ g1, const float* __restrict__ be1) {
    GEMM_PROLOG;
    BN_PREP(0, g1, be1);
    A_CPASYNC(g_scr1, 0);
#pragma unroll 1
    for (int c = 0; c < 4; c++) {
        PIPE_WAIT_SYNC;
        B_CPASYNC(g_Wimg[5][0], g_Wimg[5][1], c);
        A_TRANS_BN(out_lct, c * 64);
        PIPE_WAIT_SYNC;
        if (c < 3) A_CPASYNC(g_scr1, (c + 1) * 64);
        COMPUTE_CHUNK;
    }
    BIAS4(bb, bLC);
    STATS_DECL;
    EPI_BEGIN;
    vx += bb[ni].x;
    vy += bb[ni].y;
    STATS_ACC;
    EPI_END_STORE(g_scr2);
    STATS_REDUCE(2);
}

// k3: NE_t = leaky(bn2(g_scr2)) -> sec1; new_cell = base + ig*0.1*(NE_t@WLC+bLC) -> sec4; stats4
__global__ void __launch_bounds__(NTH, 2) k3(
    float* out_nc, float* out_net, const float* __restrict__ bLC,
    const float* __restrict__ base, const float* __restrict__ ig,
    const float* __restrict__ g2, const float* __restrict__ be2) {
    GEMM_PROLOG;
    BN_PREP(2, g2, be2);
    A_CPASYNC(g_scr2, 0);
#pragma unroll 1
    for (int c = 0; c < 4; c++) {
        PIPE_WAIT_SYNC;
        B_CPASYNC(g_Wimg[5][0], g_Wimg[5][1], c);
        A_TRANS_BN(out_net, c * 64);
        PIPE_WAIT_SYNC;
        if (c < 3) A_CPASYNC(g_scr2, (c + 1) * 64);
        COMPUTE_CHUNK;
    }
    BIAS4(bb, bLC);
    STATS_DECL;
    EPI_BEGIN;
    float2 bv = *(const float2*)(base + (size_t)rr * HD + cb);
    float2 iv = *(const float2*)(ig + (size_t)rr * HD + cb);
    vx = fmaf(iv.x * 0.1f, vx + bb[ni].x, bv.x);
    vy = fmaf(iv.y * 0.1f, vy + bb[ni].y, bv.y);
    STATS_ACC;
    EPI_END_STORE(out_nc);
    STATS_REDUCE(4);
}

// k4: C_t = leaky(bn3(sec4)) -> sec2; p = (LC_t+C_t+NE_t)@WP;
//     Pupil = sigmoid(C_t@Wo+bo)*(p+bP) -> sec3
__global__ void __launch_bounds__(NTH, 2) k4(
    const float* __restrict__ ncell, float* out_ct,
    const float* __restrict__ lct, const float* __restrict__ net,
    const float* __restrict__ bo, const float* __restrict__ WP,
    const float* __restrict__ bP, const float* __restrict__ g3,
    const float* __restrict__ be3, float* out_pupil) {
    GEMM_PROLOG;
    BN_PREP(4, g3, be3);
    float* sWP = (float*)(smem + OFF_WP);
    float* p_s = (float*)(smem + OFF_PS);
    sWP[tid] = WP[tid];
    if (tid < MT) p_s[tid] = 0.0f;
    float pv[8];
#pragma unroll
    for (int i = 0; i < 8; i++) pv[i] = 0.0f;
    A_CPASYNC(ncell, 0);
#pragma unroll 1
    for (int c = 0; c < 4; c++) {
        PIPE_WAIT_SYNC;
        B_CPASYNC(g_Wimg[6][0], g_Wimg[6][1], c);
        A_TRANS_TP(out_ct, lct, net, c * 64);
        PIPE_WAIT_SYNC;
        if (c < 3) A_CPASYNC(ncell, (c + 1) * 64);
        COMPUTE_CHUNK;
    }
    {
        const int crr = tid >> 4;
#pragma unroll
        for (int ii = 0; ii < 8; ii++) atomicAdd(&p_s[crr + ii * 16], pv[ii]);
    }
    __syncthreads();
    float bP0 = bP[0];
    BIAS4(bb, bo);
    EPI_BEGIN;
    float pr = p_s[rr - row0] + bP0;
    vx = sigm(vx + bb[ni].x) * pr;
    vy = sigm(vy + bb[ni].y) * pr;
    EPI_END_STORE(out_pupil);
}

// ---------------- launch ----------------

extern "C" void kernel_launch(void* const* d_in, const int* in_sizes, int n_in,
                              void* d_out, int out_size) {
    (void)in_sizes; (void)n_in; (void)out_size;
    const float* X    = (const float*)d_in[0];
    const float* pLC  = (const float*)d_in[1];
    const float* pC   = (const float*)d_in[2];
    const float* cell = (const float*)d_in[3];
    const float* Wx = (const float*)d_in[4];   const float* bx = (const float*)d_in[5];
    const float* Wh = (const float*)d_in[6];   const float* bh = (const float*)d_in[7];
    const float* WLC = (const float*)d_in[8];  const float* bLC = (const float*)d_in[9];
    const float* WC = (const float*)d_in[10];  const float* bC = (const float*)d_in[11];
    const float* WP = (const float*)d_in[12];  const float* bP = (const float*)d_in[13];
    const float* Wf = (const float*)d_in[14];  const float* bf = (const float*)d_in[15];
    const float* Wi = (const float*)d_in[16];  const float* bi = (const float*)d_in[17];
    const float* Wo = (const float*)d_in[18];  const float* bo = (const float*)d_in[19];
    const float* g1 = (const float*)d_in[20];  const float* be1 = (const float*)d_in[21];
    const float* g2 = (const float*)d_in[22];  const float* be2 = (const float*)d_in[23];
    const float* g3 = (const float*)d_in[24];  const float* be3 = (const float*)d_in[25];

    float* o = (float*)d_out;
    const size_t SEC = (size_t)BD * HD;
    float* sLC = o;            // LC_t   (written by k2)
    float* sNE = o + SEC;      // NE_t   (written by k3)
    float* sCT = o + 2 * SEC;  // C_t    (base until k3 consumes it; k4 writes C_t)
    float* sPU = o + 3 * SEC;  // Pupil  (igate until k3; k4 writes Pupil)
    float* sNC = o + 4 * SEC;  // new_cell (written by k3)

    // idempotent; called every time (no static guards per harness contract)
    cudaFuncSetAttribute(k1a, cudaFuncAttributeMaxDynamicSharedMemorySize, SMEM_REQ);
    cudaFuncSetAttribute(k1b, cudaFuncAttributeMaxDynamicSharedMemorySize, SMEM_REQ);
    cudaFuncSetAttribute(k1c, cudaFuncAttributeMaxDynamicSharedMemorySize, SMEM_REQ);
    cudaFuncSetAttribute(k2, cudaFuncAttributeMaxDynamicSharedMemorySize, SMEM_REQ);
    cudaFuncSetAttribute(k3, cudaFuncAttributeMaxDynamicSharedMemorySize, SMEM_REQ);
    cudaFuncSetAttribute(k4, cudaFuncAttributeMaxDynamicSharedMemorySize, SMEM_REQ);

    dim3 blk(NTH);
    dim3 grd(BD / MT, HD / NT);

    k0_prep<<<HD + 1, NTH>>>(Wx, bx, Wi, bi, WC, bC);
    kW<<<dim3(HD, 7), NTH>>>(Wx, Wh, Wf, WLC, Wo);
    k1a<<<grd, blk, SMEM_REQ>>>(X, pLC, bx, bh);
    k1b<<<grd, blk, SMEM_REQ>>>(pC, X, bf, cell, sCT);
    k1c<<<grd, blk, SMEM_REQ>>>(X, sPU);
    k2<<<grd, blk, SMEM_REQ>>>(sLC, bLC, g1, be1);
    k3<<<grd, blk, SMEM_REQ>>>(sNC, sNE, bLC, sCT, sPU, g2, be2);
    k4<<<grd, blk, SMEM_REQ>>>(sNC, sCT, sLC, sNE, bo, WP, bP, g3, be3, sPU);
}